// round 14
// baseline (speedup 1.0000x reference)
#include <cuda_runtime.h>
#include <cuda_fp16.h>

// GraphNet NodeModel, algebraically factored:
//   Xau = x @ W1a.T + Ue[batch]   (fp16 table)
//   Xb  = x @ W1b.T               (fp16 table)
//   Xc  = x @ W2a.T + b2 + Un[batch]  (fp32)
//   edge_msg = relu( Xau[dst] + Xb[src] + edge_attr @ W1c.T )
//   agg      = segment_sum(edge_msg, dst)
//   out      = relu( Xc + agg @ W2b.T )
// Edges are counting-sorted by dst; the edge kernel pre-reduces dst-runs in
// smem so red.global traffic drops ~14x. GEMMs: fp16 mma.sync + ldmatrix.

#define FD 128
#define MAXN 50000
#define MAXE 800000
#define MAXG 64

__device__ __half g_Xau[MAXN * FD];  // x @ W1[:,0:128].T + Ue[batch]
__device__ __half g_Xb16[MAXN * FD]; // x @ W1[:,128:256].T
__device__ float  g_Xc[MAXN * FD];   // x @ W2[:,0:128].T + b2 + Un[batch]
__device__ float  g_agg[MAXN * FD];  // segment-summed edge messages
__device__ float  g_Ue[MAXG * FD];
__device__ float  g_Un[MAXG * FD];
__device__ int    g_is64;

// counting-sort scratch
__device__ int g_cnt[MAXN];
__device__ int g_pos[MAXN];
__device__ int g_bsum[256];
__device__ int g_boff[256];
__device__ int g_perm[MAXE];
__device__ int g_dstS[MAXE];

// ---------------- helpers ----------------
__device__ __forceinline__ unsigned long long pack2(float x) {
    unsigned long long r;
    asm("mov.b64 %0, {%1, %1};" : "=l"(r) : "r"(__float_as_uint(x)));
    return r;
}
__device__ __forceinline__ void ffma2(unsigned long long& d,
                                      unsigned long long a,
                                      unsigned long long b) {
    asm("fma.rn.f32x2 %0, %1, %2, %0;" : "+l"(d) : "l"(a), "l"(b));
}
__device__ __forceinline__ float2 unpk(unsigned long long v) {
    float2 f;
    asm("mov.b64 {%0, %1}, %2;" : "=f"(f.x), "=f"(f.y) : "l"(v));
    return f;
}
__device__ __forceinline__ void red_add_v4(float* p, float a, float b,
                                           float c, float d) {
    unsigned long long gp = (unsigned long long)__cvta_generic_to_global(p);
    asm volatile("red.global.add.v4.f32 [%0], {%1, %2, %3, %4};"
                 :: "l"(gp), "f"(a), "f"(b), "f"(c), "f"(d) : "memory");
}
__device__ __forceinline__ long long ld_idx(const void* p, long long i, int is64) {
    if (is64) return ((const long long*)p)[i];
    return (long long)((const int*)p)[i];
}
__device__ __forceinline__ unsigned int smem_u32(const void* p) {
    unsigned int a;
    asm("{ .reg .u64 t; cvta.to.shared.u64 t, %1; cvt.u32.u64 %0, t; }"
        : "=r"(a) : "l"(p));
    return a;
}
__device__ __forceinline__ unsigned int f16pack(float2 f) {
    unsigned int h;
    asm("cvt.rn.f16x2.f32 %0, %1, %2;" : "=r"(h) : "f"(f.y), "f"(f.x));
    return h;
}
__device__ __forceinline__ void mma_f16(float& c0, float& c1, float& c2, float& c3,
                                        unsigned int a0, unsigned int a1,
                                        unsigned int a2, unsigned int a3,
                                        unsigned int b0, unsigned int b1) {
    asm volatile(
        "mma.sync.aligned.m16n8k16.row.col.f32.f16.f16.f32 "
        "{%0,%1,%2,%3}, {%4,%5,%6,%7}, {%8,%9}, {%0,%1,%2,%3};"
        : "+f"(c0), "+f"(c1), "+f"(c2), "+f"(c3)
        : "r"(a0), "r"(a1), "r"(a2), "r"(a3), "r"(b0), "r"(b1));
}
__device__ __forceinline__ void ldmatrix_x4(unsigned int& r0, unsigned int& r1,
                                            unsigned int& r2, unsigned int& r3,
                                            unsigned int addr) {
    asm volatile("ldmatrix.sync.aligned.m8n8.x4.shared.b16 {%0,%1,%2,%3}, [%4];"
                 : "=r"(r0), "=r"(r1), "=r"(r2), "=r"(r3) : "r"(addr));
}

// ---------------------------------------------------------------------------
// Index dtype sniff: int64 values < 2^31 have all-zero odd 32-bit words.
// ---------------------------------------------------------------------------
__global__ void sniff_kernel(const unsigned int* __restrict__ ei) {
    int is64 = 1;
#pragma unroll 1
    for (int k = 1; k < 129; k += 2) {
        if (ei[k] != 0u) { is64 = 0; break; }
    }
    g_is64 = is64;
}

__global__ void zero_kernel(int n4) {
    int i = blockIdx.x * blockDim.x + threadIdx.x;
    if (i < n4)
        reinterpret_cast<float4*>(g_agg)[i] = make_float4(0.f, 0.f, 0.f, 0.f);
}
__global__ void zero_cnt_kernel(int n) {
    int i = blockIdx.x * blockDim.x + threadIdx.x;
    if (i < n) g_cnt[i] = 0;
}

// ---------------- counting sort by dst ----------------
__global__ void count_kernel(const void* __restrict__ ei, int E) {
    int e = blockIdx.x * blockDim.x + threadIdx.x;
    if (e < E) {
        int d = (int)ld_idx(ei, (long long)E + e, g_is64);
        atomicAdd(&g_cnt[d], 1);
    }
}
__global__ void scan1_kernel(int n) {            // per-256-chunk sums
    __shared__ int sh[256];
    int i = blockIdx.x * 256 + threadIdx.x;
    sh[threadIdx.x] = (i < n) ? g_cnt[i] : 0;
    __syncthreads();
    for (int o = 128; o > 0; o >>= 1) {
        if (threadIdx.x < o) sh[threadIdx.x] += sh[threadIdx.x + o];
        __syncthreads();
    }
    if (threadIdx.x == 0) g_bsum[blockIdx.x] = sh[0];
}
__global__ void scan2_kernel(int nb) {           // exclusive scan of chunk sums
    __shared__ int sh[256];
    int t = threadIdx.x;
    int v = (t < nb) ? g_bsum[t] : 0;
    sh[t] = v;
    __syncthreads();
    for (int o = 1; o < 256; o <<= 1) {
        int x = (t >= o) ? sh[t - o] : 0;
        __syncthreads();
        sh[t] += x;
        __syncthreads();
    }
    if (t < nb) g_boff[t] = sh[t] - v;
}
__global__ void scan3_kernel(int n) {            // per-element exclusive offsets
    __shared__ int sh[256];
    int i = blockIdx.x * 256 + threadIdx.x;
    int v = (i < n) ? g_cnt[i] : 0;
    sh[threadIdx.x] = v;
    __syncthreads();
    for (int o = 1; o < 256; o <<= 1) {
        int x = (threadIdx.x >= o) ? sh[threadIdx.x - o] : 0;
        __syncthreads();
        sh[threadIdx.x] += x;
        __syncthreads();
    }
    if (i < n) g_pos[i] = sh[threadIdx.x] - v + g_boff[blockIdx.x];
}
__global__ void scatter_kernel(const void* __restrict__ ei, int E) {
    int e = blockIdx.x * blockDim.x + threadIdx.x;
    if (e < E) {
        int d = (int)ld_idx(ei, (long long)E + e, g_is64);
        int p = atomicAdd(&g_pos[d], 1);
        g_perm[p] = e;
        g_dstS[p] = d;
    }
}

// ---------------------------------------------------------------------------
// Per-graph GEMMs (tiny). Block = one graph, 128 threads, fp32.
// ---------------------------------------------------------------------------
__global__ void graph_kernel(const float* __restrict__ u,
                             const float* __restrict__ W1,
                             const float* __restrict__ b1,
                             const float* __restrict__ W2) {
    __shared__ float su[FD];
    int g = blockIdx.x;
    int o = threadIdx.x;
    su[o] = u[g * FD + o];
    __syncthreads();
    float a1 = b1[o];
    float a2 = 0.f;
    const float* w1r = W1 + o * 512 + 384;
    const float* w2r = W2 + o * 384 + 256;
#pragma unroll 8
    for (int k = 0; k < FD; k++) {
        a1 = fmaf(su[k], w1r[k], a1);
        a2 = fmaf(su[k], w2r[k], a2);
    }
    g_Ue[g * FD + o] = a1;
    g_Un[g * FD + o] = a2;
}

// ---------------------------------------------------------------------------
// fp16 warp-tile GEMM pieces (both operands staged to smem, stride BSTR fp16).
// ---------------------------------------------------------------------------
#define BSTR 136
#define TILE_BYTES (128 * BSTR * 2)
#define SM_B   2048
#define SM_A   (SM_B + TILE_BYTES)
#define SM_EDGE_TOTAL (SM_A + TILE_BYTES)      // 71680
#define SM_PRE_TOTAL  (2 * TILE_BYTES + 64)

__device__ __forceinline__ void stage_fp16(__half* S, const float* __restrict__ src,
                                           long long rowBase, long long M,
                                           int ldsrc, int off) {
#pragma unroll
    for (int it = 0; it < 8; it++) {
        int g = threadIdx.x + it * 256;
        int r = g >> 4;
        int c0 = (g & 15) << 3;
        uint4 out;
        long long row = rowBase + r;
        if (row < M) {
            const float4* p = reinterpret_cast<const float4*>(
                src + row * ldsrc + off + c0);
            float4 f0 = p[0], f1 = p[1];
            out = make_uint4(f16pack(make_float2(f0.x, f0.y)),
                             f16pack(make_float2(f0.z, f0.w)),
                             f16pack(make_float2(f1.x, f1.y)),
                             f16pack(make_float2(f1.z, f1.w)));
        } else {
            out = make_uint4(0u, 0u, 0u, 0u);
        }
        *reinterpret_cast<uint4*>(S + r * BSTR + c0) = out;
    }
}

// Stage with row permutation (edge kernel A). sPerm[r] = source row or -1.
__device__ __forceinline__ void stage_fp16_perm(__half* S,
                                                const float* __restrict__ src,
                                                const int* sPerm) {
#pragma unroll
    for (int it = 0; it < 8; it++) {
        int g = threadIdx.x + it * 256;
        int r = g >> 4;
        int c0 = (g & 15) << 3;
        int p = sPerm[r];
        uint4 out;
        if (p >= 0) {
            const float4* q = reinterpret_cast<const float4*>(
                src + (size_t)p * 128 + c0);
            float4 f0 = q[0], f1 = q[1];
            out = make_uint4(f16pack(make_float2(f0.x, f0.y)),
                             f16pack(make_float2(f0.z, f0.w)),
                             f16pack(make_float2(f1.x, f1.y)),
                             f16pack(make_float2(f1.z, f1.w)));
        } else {
            out = make_uint4(0u, 0u, 0u, 0u);
        }
        *reinterpret_cast<uint4*>(S + r * BSTR + c0) = out;
    }
}

__device__ __forceinline__ void mma_mainloop_sm(
    unsigned int sbA, unsigned int sbB, int wid, int lane, float (&acc)[16][4])
{
    unsigned int abase = sbA
        + (unsigned int)((wid * 16 + (lane & 15)) * (BSTR * 2))
        + (unsigned int)((lane >> 4) * 16);

    unsigned int bbase[8];
    {
        int ii = lane & 7;
        int gg = lane >> 3;
        int nthalf = gg >> 1;
        int khalf = gg & 1;
#pragma unroll
        for (int q = 0; q < 8; q++) {
            int row = (2 * q + nthalf) * 8 + ii;
            bbase[q] = sbB + (unsigned int)(row * (BSTR * 2)) + khalf * 16;
        }
    }

#pragma unroll
    for (int kc = 0; kc < 8; kc++) {
        const int koff = kc * 32;
        unsigned int a0, a1, a2, a3;
        ldmatrix_x4(a0, a1, a2, a3, abase + koff);
#pragma unroll
        for (int q = 0; q < 8; q++) {
            unsigned int b0, b1, b2, b3;
            ldmatrix_x4(b0, b1, b2, b3, bbase[q] + koff);
            mma_f16(acc[2*q][0],   acc[2*q][1],   acc[2*q][2],   acc[2*q][3],
                    a0, a1, a2, a3, b0, b1);
            mma_f16(acc[2*q+1][0], acc[2*q+1][1], acc[2*q+1][2], acc[2*q+1][3],
                    a0, a1, a2, a3, b2, b3);
        }
    }
}

// ---------------------------------------------------------------------------
// Precompute Xau / Xb16 / Xc; grid.y selects product.
// ---------------------------------------------------------------------------
__global__ __launch_bounds__(256, 2)
void precompute_mma_kernel(const float* __restrict__ x,
                           const float* __restrict__ W1,
                           const float* __restrict__ W2,
                           const float* __restrict__ b2,
                           const void* __restrict__ batch, int N)
{
    extern __shared__ __align__(16) char smem[];
    __half* Bh = (__half*)smem;
    __half* Ah = (__half*)(smem + TILE_BYTES);

    const float* W; int ldw, off;
    int which = blockIdx.y;
    if (which == 0)      { W = W1; ldw = 512; off = 0;   }
    else if (which == 1) { W = W1; ldw = 512; off = 128; }
    else                 { W = W2; ldw = 384; off = 0;   }

    const long long m0 = (long long)blockIdx.x * 128;
    stage_fp16(Bh, W, 0, 128, ldw, off);
    stage_fp16(Ah, x, m0, N, 128, 0);
    __syncthreads();

    const int tid = threadIdx.x;
    const int wid = tid >> 5;
    const int lane = tid & 31;
    const long long r0 = m0 + wid * 16 + (lane >> 2);
    const long long r1 = r0 + 8;

    float acc[16][4];
#pragma unroll
    for (int t = 0; t < 16; t++)
#pragma unroll
        for (int j = 0; j < 4; j++) acc[t][j] = 0.f;

    mma_mainloop_sm(smem_u32(Ah), smem_u32(Bh), wid, lane, acc);

    const int cb = (lane & 3) * 2;
    const int is64 = g_is64;
#pragma unroll
    for (int h = 0; h < 2; h++) {
        long long row = h ? r1 : r0;
        if (row >= N) continue;
        const float* uadd = 0;
        if (which == 0)
            uadd = g_Ue + (size_t)ld_idx(batch, row, is64) * 128;
        else if (which == 2)
            uadd = g_Un + (size_t)ld_idx(batch, row, is64) * 128;
#pragma unroll
        for (int nt = 0; nt < 16; nt++) {
            int c = nt * 8 + cb;
            float vx = acc[nt][2 * h], vy = acc[nt][2 * h + 1];
            if (uadd) { vx += uadd[c]; vy += uadd[c + 1]; }
            if (which == 2) {
                vx += b2[c]; vy += b2[c + 1];
                *reinterpret_cast<float2*>(g_Xc + row * 128 + c) = make_float2(vx, vy);
            } else {
                __half2 hv = __floats2half2_rn(vx, vy);
                __half* T = (which == 0) ? g_Xau : g_Xb16;
                *reinterpret_cast<__half2*>(T + row * 128 + c) = hv;
            }
        }
    }
}

// ---------------------------------------------------------------------------
// Edge kernel (dst-sorted): 128 edges/block via g_perm. GEMM as before;
// epilogue computes w in smem, run-leaders segment-reduce, one red per run.
// ---------------------------------------------------------------------------
__global__ __launch_bounds__(256, 2)
void edge_mma_kernel(const float* __restrict__ edge_attr,
                     const void* __restrict__ ei,
                     const float* __restrict__ W1, int E)
{
    extern __shared__ __align__(16) char smem[];
    int* sDst  = (int*)smem;            // [128]
    int* sSrc  = sDst + 128;            // [128]
    int* sPerm = sSrc + 128;            // [128]
    __half* Bh = (__half*)(smem + SM_B);
    __half* Ah = (__half*)(smem + SM_A);
    float* Cbuf = (float*)(smem + SM_B);   // [128][132], aliases A+B

    const int tid = threadIdx.x;
    const int wid = tid >> 5;
    const int lane = tid & 31;
    const long long e0 = (long long)blockIdx.x * 128;

    if (tid < 128) {
        long long pos = e0 + tid;
        if (pos < E) {
            int p = g_perm[pos];
            sPerm[tid] = p;
            sDst[tid] = g_dstS[pos];
            sSrc[tid] = (int)ld_idx(ei, p, g_is64);
        } else {
            sPerm[tid] = -1; sDst[tid] = -1; sSrc[tid] = 0;
        }
    }
    __syncthreads();

    stage_fp16(Bh, W1, 0, 128, 512, 256);     // W1c = W1[:,256:384]
    stage_fp16_perm(Ah, edge_attr, sPerm);
    __syncthreads();

    float acc[16][4];
#pragma unroll
    for (int t = 0; t < 16; t++)
#pragma unroll
        for (int j = 0; j < 4; j++) acc[t][j] = 0.f;

    mma_mainloop_sm(smem_u32(Ah), smem_u32(Bh), wid, lane, acc);

    // stage C to smem (A/B dead)
    __syncthreads();
    {
        const int rbase = wid * 16 + (lane >> 2);
        const int cb = (lane & 3) * 2;
#pragma unroll
        for (int nt = 0; nt < 16; nt++) {
            float* p0 = Cbuf + rbase * 132 + nt * 8 + cb;
            *reinterpret_cast<float2*>(p0)           = make_float2(acc[nt][0], acc[nt][1]);
            *reinterpret_cast<float2*>(p0 + 8 * 132) = make_float2(acc[nt][2], acc[nt][3]);
        }
    }
    __syncthreads();

    // w = relu(Ea + Xau[dst] + Xb[src]) written in place (2 threads/edge)
    const int el = tid >> 1;
    const int cb = (tid & 1) * 64;
    const bool valid = (e0 + el) < E;
    const int d = valid ? sDst[el] : -1;
    if (valid) {
        int s = sSrc[el];
        const __half* xa = g_Xau + (size_t)d * 128 + cb;
        const __half* xb = g_Xb16 + (size_t)s * 128 + cb;
        float* cr = Cbuf + el * 132 + cb;
#pragma unroll
        for (int j = 0; j < 8; j++) {
            int c = j * 8;
            float4 m0 = *reinterpret_cast<const float4*>(cr + c);
            float4 m1 = *reinterpret_cast<const float4*>(cr + c + 4);
            uint4 ua = *reinterpret_cast<const uint4*>(xa + c);
            uint4 ub = *reinterpret_cast<const uint4*>(xb + c);
            float2 a0 = __half22float2(*reinterpret_cast<__half2*>(&ua.x));
            float2 a1 = __half22float2(*reinterpret_cast<__half2*>(&ua.y));
            float2 a2 = __half22float2(*reinterpret_cast<__half2*>(&ua.z));
            float2 a3 = __half22float2(*reinterpret_cast<__half2*>(&ua.w));
            float2 b0 = __half22float2(*reinterpret_cast<__half2*>(&ub.x));
            float2 b1 = __half22float2(*reinterpret_cast<__half2*>(&ub.y));
            float2 b2 = __half22float2(*reinterpret_cast<__half2*>(&ub.z));
            float2 b3 = __half22float2(*reinterpret_cast<__half2*>(&ub.w));
            float4 w0, w1;
            w0.x = fmaxf(m0.x + a0.x + b0.x, 0.f);
            w0.y = fmaxf(m0.y + a0.y + b0.y, 0.f);
            w0.z = fmaxf(m0.z + a1.x + b1.x, 0.f);
            w0.w = fmaxf(m0.w + a1.y + b1.y, 0.f);
            w1.x = fmaxf(m1.x + a2.x + b2.x, 0.f);
            w1.y = fmaxf(m1.y + a2.y + b2.y, 0.f);
            w1.z = fmaxf(m1.z + a3.x + b3.x, 0.f);
            w1.w = fmaxf(m1.w + a3.y + b3.y, 0.f);
            *reinterpret_cast<float4*>(cr + c)     = w0;
            *reinterpret_cast<float4*>(cr + c + 4) = w1;
        }
    }
    __syncthreads();

    // run-leaders: sum run rows in smem, one red.v4 set per run per half
    if (valid && (el == 0 || sDst[el - 1] != d)) {
        const float* cr = Cbuf + el * 132 + cb;
        float4 s16[16];
#pragma unroll
        for (int j = 0; j < 16; j++)
            s16[j] = *reinterpret_cast<const float4*>(cr + j * 4);
        int r = el + 1;
        while (r < 128 && sDst[r] == d) {
            const float* crr = Cbuf + r * 132 + cb;
#pragma unroll
            for (int j = 0; j < 16; j++) {
                float4 v = *reinterpret_cast<const float4*>(crr + j * 4);
                s16[j].x += v.x; s16[j].y += v.y;
                s16[j].z += v.z; s16[j].w += v.w;
            }
            r++;
        }
        float* dp = g_agg + (size_t)d * 128 + cb;
#pragma unroll
        for (int j = 0; j < 16; j++)
            red_add_v4(dp + j * 4, s16[j].x, s16[j].y, s16[j].z, s16[j].w);
    }
}

// ---------------------------------------------------------------------------
// FFMA2 tile GEMM (node kernel): 128x128xK=128, 256 threads. fp32 exact.
// ---------------------------------------------------------------------------
__device__ __forceinline__ void tile_gemm(
    const float* __restrict__ A, int rowBase, int M,
    const float* __restrict__ W, int ldw, int off,
    unsigned long long (&acc)[8][4], float (*As)[132], float (*Bs)[132])
{
    const int tid = threadIdx.x;
    const int le = tid & 127;
    const int lq = (tid >> 7) << 3;
    const int tx = tid & 15;
    const int ty = tid >> 4;

#pragma unroll 1
    for (int k0 = 0; k0 < 128; k0 += 16) {
        float4 v0, v1;
        int row = rowBase + le;
        if (row < M) {
            const float4* p = reinterpret_cast<const float4*>(
                A + (size_t)row * 128 + k0 + lq);
            v0 = p[0]; v1 = p[1];
        } else {
            v0 = make_float4(0.f, 0.f, 0.f, 0.f); v1 = v0;
        }
        const float4* q = reinterpret_cast<const float4*>(
            W + (size_t)le * ldw + off + k0 + lq);
        float4 w0 = q[0], w1 = q[1];

        __syncthreads();
        As[lq + 0][le] = v0.x; As[lq + 1][le] = v0.y;
        As[lq + 2][le] = v0.z; As[lq + 3][le] = v0.w;
        As[lq + 4][le] = v1.x; As[lq + 5][le] = v1.y;
        As[lq + 6][le] = v1.z; As[lq + 7][le] = v1.w;
        Bs[lq + 0][le] = w0.x; Bs[lq + 1][le] = w0.y;
        Bs[lq + 2][le] = w0.z; Bs[lq + 3][le] = w0.w;
        Bs[lq + 4][le] = w1.x; Bs[lq + 5][le] = w1.y;
        Bs[lq + 6][le] = w1.z; Bs[lq + 7][le] = w1.w;
        __syncthreads();

#pragma unroll
        for (int kk = 0; kk < 16; kk++) {
            float4 a0 = *reinterpret_cast<const float4*>(&As[kk][ty * 8]);
            float4 a1 = *reinterpret_cast<const float4*>(&As[kk][ty * 8 + 4]);
            ulonglong2 b01 = *reinterpret_cast<const ulonglong2*>(&Bs[kk][tx * 8]);
            ulonglong2 b23 = *reinterpret_cast<const ulonglong2*>(&Bs[kk][tx * 8 + 4]);
            unsigned long long av[8];
            av[0] = pack2(a0.x); av[1] = pack2(a0.y);
            av[2] = pack2(a0.z); av[3] = pack2(a0.w);
            av[4] = pack2(a1.x); av[5] = pack2(a1.y);
            av[6] = pack2(a1.z); av[7] = pack2(a1.w);
            unsigned long long bv[4] = {b01.x, b01.y, b23.x, b23.y};
#pragma unroll
            for (int i = 0; i < 8; i++)
#pragma unroll
                for (int j = 0; j < 4; j++)
                    ffma2(acc[i][j], av[i], bv[j]);
        }
    }
    __syncthreads();
}

// ---------------------------------------------------------------------------
// Node kernel: out = relu( Xc + agg @ W2[:,128:256].T )
// ---------------------------------------------------------------------------
__global__ __launch_bounds__(256) void node_kernel(
    const float* __restrict__ W2, float* __restrict__ out, int N)
{
    __shared__ __align__(16) float As[16][132];
    __shared__ __align__(16) float Bs[16][132];

    int n0 = blockIdx.x * 128;
    unsigned long long acc[8][4];
#pragma unroll
    for (int i = 0; i < 8; i++)
#pragma unroll
        for (int j = 0; j < 4; j++) acc[i][j] = 0ull;

    tile_gemm(g_agg, n0, N, W2, 384, 128, acc, As, Bs);

    int tid = threadIdx.x;
    int tx = tid & 15, ty = tid >> 4;
    int c = tx * 8;
#pragma unroll
    for (int i = 0; i < 8; i++) {
        int row = n0 + ty * 8 + i;
        if (row < N) {
            const float4* pc = reinterpret_cast<const float4*>(&g_Xc[(size_t)row * 128 + c]);
            float4 c0 = pc[0], c1 = pc[1];
            float2 p0 = unpk(acc[i][0]), p1 = unpk(acc[i][1]);
            float2 p2 = unpk(acc[i][2]), p3 = unpk(acc[i][3]);
            float4 o0, o1;
            o0.x = fmaxf(p0.x + c0.x, 0.f);
            o0.y = fmaxf(p0.y + c0.y, 0.f);
            o0.z = fmaxf(p1.x + c0.z, 0.f);
            o0.w = fmaxf(p1.y + c0.w, 0.f);
            o1.x = fmaxf(p2.x + c1.x, 0.f);
            o1.y = fmaxf(p2.y + c1.y, 0.f);
            o1.z = fmaxf(p3.x + c1.z, 0.f);
            o1.w = fmaxf(p3.y + c1.w, 0.f);
            float4* po = reinterpret_cast<float4*>(&out[(size_t)row * 128 + c]);
            po[0] = o0; po[1] = o1;
        }
    }
}

// ---------------------------------------------------------------------------
// Launch. Inputs: x, edge_index, edge_attr, u, batch, W1, b1, W2, b2.
// ---------------------------------------------------------------------------
extern "C" void kernel_launch(void* const* d_in, const int* in_sizes, int n_in,
                              void* d_out, int out_size) {
    const float* x         = (const float*)d_in[0];
    const void*  ei        = d_in[1];
    const float* edge_attr = (const float*)d_in[2];
    const float* u         = (const float*)d_in[3];
    const void*  batch     = d_in[4];
    const float* W1        = (const float*)d_in[5];
    const float* b1        = (const float*)d_in[6];
    const float* W2        = (const float*)d_in[7];
    const float* b2        = (const float*)d_in[8];
    float* out = (float*)d_out;

    int N = in_sizes[0] / FD;
    int E = in_sizes[2] / FD;
    int G = in_sizes[3] / FD;

    cudaFuncSetAttribute(edge_mma_kernel,
                         cudaFuncAttributeMaxDynamicSharedMemorySize, SM_EDGE_TOTAL);
    cudaFuncSetAttribute(precompute_mma_kernel,
                         cudaFuncAttributeMaxDynamicSharedMemorySize, SM_PRE_TOTAL);

    sniff_kernel<<<1, 1>>>((const unsigned int*)ei);

    int n4 = N * (FD / 4);
    zero_kernel<<<(n4 + 255) / 256, 256>>>(n4);
    zero_cnt_kernel<<<(N + 255) / 256, 256>>>(N);

    // counting sort of edges by dst
    int nb = (N + 255) / 256;
    count_kernel<<<(E + 255) / 256, 256>>>(ei, E);
    scan1_kernel<<<nb, 256>>>(N);
    scan2_kernel<<<1, 256>>>(nb);
    scan3_kernel<<<nb, 256>>>(N);
    scatter_kernel<<<(E + 255) / 256, 256>>>(ei, E);

    graph_kernel<<<G, FD>>>(u, W1, b1, W2);

    dim3 pg((N + 127) / 128, 3);
    precompute_mma_kernel<<<pg, 256, SM_PRE_TOTAL>>>(x, W1, W2, b2, batch, N);

    edge_mma_kernel<<<(E + 127) / 128, 256, SM_EDGE_TOTAL>>>(edge_attr, ei, W1, E);

    node_kernel<<<(N + 127) / 128, 256>>>(W2, out, N);
}

// round 15
// speedup vs baseline: 1.0117x; 1.0117x over previous
#include <cuda_runtime.h>
#include <cuda_fp16.h>

// GraphNet NodeModel, algebraically factored:
//   Xau = x @ W1a.T + Ue[batch]   (fp16 table)
//   Xb  = x @ W1b.T               (fp16 table)
//   Xc  = x @ W2a.T + b2 + Un[batch]  (fp32)
//   edge_msg = relu( Xau[dst] + Xb[src] + edge_attr @ W1c.T )
//   agg      = segment_sum(edge_msg, dst)   (red.global.add.v4.f32)
//   out      = relu( Xc + agg @ W2b.T )
// Edge kernel: PERSISTENT blocks, B staged once, stage-A(t+1) fused with
// epilogue(t) for latency overlap. GEMMs: fp16 mma.sync + ldmatrix.

#define FD 128
#define MAXN 50000
#define MAXG 64

__device__ __half g_Xau[MAXN * FD];  // x @ W1[:,0:128].T + Ue[batch]
__device__ __half g_Xb16[MAXN * FD]; // x @ W1[:,128:256].T
__device__ float  g_Xc[MAXN * FD];   // x @ W2[:,0:128].T + b2 + Un[batch]
__device__ float  g_agg[MAXN * FD];  // segment-summed edge messages
__device__ float  g_Ue[MAXG * FD];
__device__ float  g_Un[MAXG * FD];
__device__ int    g_is64;

// ---------------- helpers ----------------
__device__ __forceinline__ unsigned long long pack2(float x) {
    unsigned long long r;
    asm("mov.b64 %0, {%1, %1};" : "=l"(r) : "r"(__float_as_uint(x)));
    return r;
}
__device__ __forceinline__ void ffma2(unsigned long long& d,
                                      unsigned long long a,
                                      unsigned long long b) {
    asm("fma.rn.f32x2 %0, %1, %2, %0;" : "+l"(d) : "l"(a), "l"(b));
}
__device__ __forceinline__ float2 unpk(unsigned long long v) {
    float2 f;
    asm("mov.b64 {%0, %1}, %2;" : "=f"(f.x), "=f"(f.y) : "l"(v));
    return f;
}
__device__ __forceinline__ void red_add_v4(float* p, float a, float b,
                                           float c, float d) {
    unsigned long long gp = (unsigned long long)__cvta_generic_to_global(p);
    asm volatile("red.global.add.v4.f32 [%0], {%1, %2, %3, %4};"
                 :: "l"(gp), "f"(a), "f"(b), "f"(c), "f"(d) : "memory");
}
__device__ __forceinline__ long long ld_idx(const void* p, long long i, int is64) {
    if (is64) return ((const long long*)p)[i];
    return (long long)((const int*)p)[i];
}
__device__ __forceinline__ unsigned int smem_u32(const void* p) {
    unsigned int a;
    asm("{ .reg .u64 t; cvta.to.shared.u64 t, %1; cvt.u32.u64 %0, t; }"
        : "=r"(a) : "l"(p));
    return a;
}
__device__ __forceinline__ unsigned int f16pack(float2 f) {
    unsigned int h;
    asm("cvt.rn.f16x2.f32 %0, %1, %2;" : "=r"(h) : "f"(f.y), "f"(f.x));
    return h;
}
__device__ __forceinline__ void mma_f16(float& c0, float& c1, float& c2, float& c3,
                                        unsigned int a0, unsigned int a1,
                                        unsigned int a2, unsigned int a3,
                                        unsigned int b0, unsigned int b1) {
    asm volatile(
        "mma.sync.aligned.m16n8k16.row.col.f32.f16.f16.f32 "
        "{%0,%1,%2,%3}, {%4,%5,%6,%7}, {%8,%9}, {%0,%1,%2,%3};"
        : "+f"(c0), "+f"(c1), "+f"(c2), "+f"(c3)
        : "r"(a0), "r"(a1), "r"(a2), "r"(a3), "r"(b0), "r"(b1));
}
__device__ __forceinline__ void ldmatrix_x4(unsigned int& r0, unsigned int& r1,
                                            unsigned int& r2, unsigned int& r3,
                                            unsigned int addr) {
    asm volatile("ldmatrix.sync.aligned.m8n8.x4.shared.b16 {%0,%1,%2,%3}, [%4];"
                 : "=r"(r0), "=r"(r1), "=r"(r2), "=r"(r3) : "r"(addr));
}

// ---------------------------------------------------------------------------
// Index dtype sniff: int64 values < 2^31 have all-zero odd 32-bit words.
// ---------------------------------------------------------------------------
__global__ void sniff_kernel(const unsigned int* __restrict__ ei) {
    int is64 = 1;
#pragma unroll 1
    for (int k = 1; k < 129; k += 2) {
        if (ei[k] != 0u) { is64 = 0; break; }
    }
    g_is64 = is64;
}

__global__ void zero_kernel(int n4) {
    int i = blockIdx.x * blockDim.x + threadIdx.x;
    if (i < n4)
        reinterpret_cast<float4*>(g_agg)[i] = make_float4(0.f, 0.f, 0.f, 0.f);
}

// ---------------------------------------------------------------------------
// Per-graph GEMMs (tiny). Block = one graph, 128 threads, fp32.
// ---------------------------------------------------------------------------
__global__ void graph_kernel(const float* __restrict__ u,
                             const float* __restrict__ W1,
                             const float* __restrict__ b1,
                             const float* __restrict__ W2) {
    __shared__ float su[FD];
    int g = blockIdx.x;
    int o = threadIdx.x;
    su[o] = u[g * FD + o];
    __syncthreads();
    float a1 = b1[o];
    float a2 = 0.f;
    const float* w1r = W1 + o * 512 + 384;
    const float* w2r = W2 + o * 384 + 256;
#pragma unroll 8
    for (int k = 0; k < FD; k++) {
        a1 = fmaf(su[k], w1r[k], a1);
        a2 = fmaf(su[k], w2r[k], a2);
    }
    g_Ue[g * FD + o] = a1;
    g_Un[g * FD + o] = a2;
}

// ---------------------------------------------------------------------------
// fp16 warp-tile GEMM pieces. A/B staged to smem, stride BSTR fp16.
// ---------------------------------------------------------------------------
#define BSTR 136
#define TILE_BYTES (128 * BSTR * 2)            // 34816
#define CSTR 132
#define CF_BYTES (128 * CSTR * 2)              // 33792
#define SM_EDGE_TOTAL (2 * TILE_BYTES + CF_BYTES)   // 103424
#define SM_PRE_TOTAL  (2 * TILE_BYTES + 64)

__device__ __forceinline__ void stage_fp16(__half* S, const float* __restrict__ src,
                                           long long rowBase, long long M,
                                           int ldsrc, int off) {
#pragma unroll
    for (int it = 0; it < 8; it++) {
        int g = threadIdx.x + it * 256;
        int r = g >> 4;
        int c0 = (g & 15) << 3;
        uint4 out;
        long long row = rowBase + r;
        if (row < M) {
            const float4* p = reinterpret_cast<const float4*>(
                src + row * ldsrc + off + c0);
            float4 f0 = p[0], f1 = p[1];
            out = make_uint4(f16pack(make_float2(f0.x, f0.y)),
                             f16pack(make_float2(f0.z, f0.w)),
                             f16pack(make_float2(f1.x, f1.y)),
                             f16pack(make_float2(f1.z, f1.w)));
        } else {
            out = make_uint4(0u, 0u, 0u, 0u);
        }
        *reinterpret_cast<uint4*>(S + r * BSTR + c0) = out;
    }
}

__device__ __forceinline__ void mma_mainloop_sm(
    unsigned int sbA, unsigned int sbB, int wid, int lane, float (&acc)[16][4])
{
    unsigned int abase = sbA
        + (unsigned int)((wid * 16 + (lane & 15)) * (BSTR * 2))
        + (unsigned int)((lane >> 4) * 16);

    unsigned int bbase[8];
    {
        int ii = lane & 7;
        int gg = lane >> 3;
        int nthalf = gg >> 1;
        int khalf = gg & 1;
#pragma unroll
        for (int q = 0; q < 8; q++) {
            int row = (2 * q + nthalf) * 8 + ii;
            bbase[q] = sbB + (unsigned int)(row * (BSTR * 2)) + khalf * 16;
        }
    }

#pragma unroll
    for (int kc = 0; kc < 8; kc++) {
        const int koff = kc * 32;
        unsigned int a0, a1, a2, a3;
        ldmatrix_x4(a0, a1, a2, a3, abase + koff);
#pragma unroll
        for (int q = 0; q < 8; q++) {
            unsigned int b0, b1, b2, b3;
            ldmatrix_x4(b0, b1, b2, b3, bbase[q] + koff);
            mma_f16(acc[2*q][0],   acc[2*q][1],   acc[2*q][2],   acc[2*q][3],
                    a0, a1, a2, a3, b0, b1);
            mma_f16(acc[2*q+1][0], acc[2*q+1][1], acc[2*q+1][2], acc[2*q+1][3],
                    a0, a1, a2, a3, b2, b3);
        }
    }
}

// ---------------------------------------------------------------------------
// Precompute Xau / Xb16 / Xc; grid.y selects product.
// ---------------------------------------------------------------------------
__global__ __launch_bounds__(256, 2)
void precompute_mma_kernel(const float* __restrict__ x,
                           const float* __restrict__ W1,
                           const float* __restrict__ W2,
                           const float* __restrict__ b2,
                           const void* __restrict__ batch, int N)
{
    extern __shared__ __align__(16) char smem[];
    __half* Bh = (__half*)smem;
    __half* Ah = (__half*)(smem + TILE_BYTES);

    const float* W; int ldw, off;
    int which = blockIdx.y;
    if (which == 0)      { W = W1; ldw = 512; off = 0;   }
    else if (which == 1) { W = W1; ldw = 512; off = 128; }
    else                 { W = W2; ldw = 384; off = 0;   }

    const long long m0 = (long long)blockIdx.x * 128;
    stage_fp16(Bh, W, 0, 128, ldw, off);
    stage_fp16(Ah, x, m0, N, 128, 0);
    __syncthreads();

    const int tid = threadIdx.x;
    const int wid = tid >> 5;
    const int lane = tid & 31;
    const long long r0 = m0 + wid * 16 + (lane >> 2);
    const long long r1 = r0 + 8;

    float acc[16][4];
#pragma unroll
    for (int t = 0; t < 16; t++)
#pragma unroll
        for (int j = 0; j < 4; j++) acc[t][j] = 0.f;

    mma_mainloop_sm(smem_u32(Ah), smem_u32(Bh), wid, lane, acc);

    const int cb = (lane & 3) * 2;
    const int is64 = g_is64;
#pragma unroll
    for (int h = 0; h < 2; h++) {
        long long row = h ? r1 : r0;
        if (row >= N) continue;
        const float* uadd = 0;
        if (which == 0)
            uadd = g_Ue + (size_t)ld_idx(batch, row, is64) * 128;
        else if (which == 2)
            uadd = g_Un + (size_t)ld_idx(batch, row, is64) * 128;
#pragma unroll
        for (int nt = 0; nt < 16; nt++) {
            int c = nt * 8 + cb;
            float vx = acc[nt][2 * h], vy = acc[nt][2 * h + 1];
            if (uadd) { vx += uadd[c]; vy += uadd[c + 1]; }
            if (which == 2) {
                vx += b2[c]; vy += b2[c + 1];
                *reinterpret_cast<float2*>(g_Xc + row * 128 + c) = make_float2(vx, vy);
            } else {
                __half2 hv = __floats2half2_rn(vx, vy);
                __half* T = (which == 0) ? g_Xau : g_Xb16;
                *reinterpret_cast<__half2*>(T + row * 128 + c) = hv;
            }
        }
    }
}

// ---------------------------------------------------------------------------
// Persistent edge kernel. Layout: Bh | Ah | Cf (fp16, [128][CSTR]).
// Per tile: mma -> Cf -> sync -> {issue stage-A(t+1) LDGs, epilogue(t),
// cvt+STS stage-A} -> sync.
// ---------------------------------------------------------------------------
__global__ __launch_bounds__(256, 2)
void edge_persist_kernel(const float* __restrict__ edge_attr,
                         const void* __restrict__ ei,
                         const float* __restrict__ W1, int E)
{
    extern __shared__ __align__(16) char smem[];
    __half* Bh = (__half*)smem;
    __half* Ah = (__half*)(smem + TILE_BYTES);
    __half* Cf = (__half*)(smem + 2 * TILE_BYTES);

    const int tid = threadIdx.x;
    const int wid = tid >> 5;
    const int lane = tid & 31;
    const int is64 = g_is64;
    const long long nT = ((long long)E + 127) >> 7;

    stage_fp16(Bh, W1, 0, 128, 512, 256);     // W1c = W1[:,256:384], once

    long long tile = blockIdx.x;
    if (tile < nT)
        stage_fp16(Ah, edge_attr, tile << 7, E, 128, 0);
    __syncthreads();

    const unsigned int sbA = smem_u32(Ah), sbB = smem_u32(Bh);

    while (tile < nT) {
        const long long e0 = tile << 7;

        float acc[16][4];
#pragma unroll
        for (int t = 0; t < 16; t++)
#pragma unroll
            for (int j = 0; j < 4; j++) acc[t][j] = 0.f;

        mma_mainloop_sm(sbA, sbB, wid, lane, acc);

        // write C (fp16) to its own buffer
        {
            const int rbase = wid * 16 + (lane >> 2);
            const int cb = (lane & 3) * 2;
#pragma unroll
            for (int nt = 0; nt < 16; nt++) {
                __half2 h0 = __floats2half2_rn(acc[nt][0], acc[nt][1]);
                __half2 h1 = __floats2half2_rn(acc[nt][2], acc[nt][3]);
                *reinterpret_cast<__half2*>(Cf + rbase * CSTR + nt * 8 + cb) = h0;
                *reinterpret_cast<__half2*>(Cf + (rbase + 8) * CSTR + nt * 8 + cb) = h1;
            }
        }
        __syncthreads();   // Cf visible; all warps done with Ah

        const long long nxt = tile + gridDim.x;
        const bool has_next = nxt < nT;
        const long long nb = nxt << 7;

        // --- issue stage-A(t+1) loads into registers (reuses dead acc regs) ---
        float4 sv0[8], sv1[8];
        if (has_next) {
#pragma unroll
            for (int it = 0; it < 8; it++) {
                int g = tid + it * 256;
                int r = g >> 4;
                int c0 = (g & 15) << 3;
                long long row = nb + r;
                if (row < E) {
                    const float4* p = reinterpret_cast<const float4*>(
                        edge_attr + row * 128 + c0);
                    sv0[it] = p[0]; sv1[it] = p[1];
                } else {
                    sv0[it] = make_float4(0.f, 0.f, 0.f, 0.f); sv1[it] = sv0[it];
                }
            }
        }

        // --- epilogue(t): gathers + relu + red (2 threads per edge) ---
        {
            const int el = tid >> 1;
            const int cb = (tid & 1) * 64;
            const long long ge = e0 + el;
            if (ge < E) {
                int s = (int)ld_idx(ei, ge, is64);
                int d = (int)ld_idx(ei, (long long)E + ge, is64);
                const __half* xa = g_Xau + (size_t)d * 128 + cb;
                const __half* xb = g_Xb16 + (size_t)s * 128 + cb;
                const __half* cr = Cf + el * CSTR + cb;
                float* dp = g_agg + (size_t)d * 128 + cb;
#pragma unroll
                for (int j = 0; j < 8; j++) {
                    int c = j * 8;
                    uint2 mA = *reinterpret_cast<const uint2*>(cr + c);
                    uint2 mB = *reinterpret_cast<const uint2*>(cr + c + 4);
                    uint4 ua = *reinterpret_cast<const uint4*>(xa + c);
                    uint4 ub = *reinterpret_cast<const uint4*>(xb + c);
                    float2 m0 = __half22float2(*reinterpret_cast<__half2*>(&mA.x));
                    float2 m1 = __half22float2(*reinterpret_cast<__half2*>(&mA.y));
                    float2 m2 = __half22float2(*reinterpret_cast<__half2*>(&mB.x));
                    float2 m3 = __half22float2(*reinterpret_cast<__half2*>(&mB.y));
                    float2 a0 = __half22float2(*reinterpret_cast<__half2*>(&ua.x));
                    float2 a1 = __half22float2(*reinterpret_cast<__half2*>(&ua.y));
                    float2 a2 = __half22float2(*reinterpret_cast<__half2*>(&ua.z));
                    float2 a3 = __half22float2(*reinterpret_cast<__half2*>(&ua.w));
                    float2 b0 = __half22float2(*reinterpret_cast<__half2*>(&ub.x));
                    float2 b1 = __half22float2(*reinterpret_cast<__half2*>(&ub.y));
                    float2 b2 = __half22float2(*reinterpret_cast<__half2*>(&ub.z));
                    float2 b3 = __half22float2(*reinterpret_cast<__half2*>(&ub.w));
                    float w0 = fmaxf(m0.x + a0.x + b0.x, 0.f);
                    float w1 = fmaxf(m0.y + a0.y + b0.y, 0.f);
                    float w2 = fmaxf(m1.x + a1.x + b1.x, 0.f);
                    float w3 = fmaxf(m1.y + a1.y + b1.y, 0.f);
                    red_add_v4(dp + c, w0, w1, w2, w3);
                    float w4 = fmaxf(m2.x + a2.x + b2.x, 0.f);
                    float w5 = fmaxf(m2.y + a2.y + b2.y, 0.f);
                    float w6 = fmaxf(m3.x + a3.x + b3.x, 0.f);
                    float w7 = fmaxf(m3.y + a3.y + b3.y, 0.f);
                    red_add_v4(dp + c + 4, w4, w5, w6, w7);
                }
            }
        }

        // --- convert + store stage-A(t+1) ---
        if (has_next) {
#pragma unroll
            for (int it = 0; it < 8; it++) {
                int g = tid + it * 256;
                int r = g >> 4;
                int c0 = (g & 15) << 3;
                uint4 out = make_uint4(
                    f16pack(make_float2(sv0[it].x, sv0[it].y)),
                    f16pack(make_float2(sv0[it].z, sv0[it].w)),
                    f16pack(make_float2(sv1[it].x, sv1[it].y)),
                    f16pack(make_float2(sv1[it].z, sv1[it].w)));
                *reinterpret_cast<uint4*>(Ah + r * BSTR + c0) = out;
            }
        }
        __syncthreads();
        tile = nxt;
    }
}

// ---------------------------------------------------------------------------
// FFMA2 tile GEMM (node kernel): 128x128xK=128, 256 threads. fp32 exact.
// ---------------------------------------------------------------------------
__device__ __forceinline__ void tile_gemm(
    const float* __restrict__ A, int rowBase, int M,
    const float* __restrict__ W, int ldw, int off,
    unsigned long long (&acc)[8][4], float (*As)[132], float (*Bs)[132])
{
    const int tid = threadIdx.x;
    const int le = tid & 127;
    const int lq = (tid >> 7) << 3;
    const int tx = tid & 15;
    const int ty = tid >> 4;

#pragma unroll 1
    for (int k0 = 0; k0 < 128; k0 += 16) {
        float4 v0, v1;
        int row = rowBase + le;
        if (row < M) {
            const float4* p = reinterpret_cast<const float4*>(
                A + (size_t)row * 128 + k0 + lq);
            v0 = p[0]; v1 = p[1];
        } else {
            v0 = make_float4(0.f, 0.f, 0.f, 0.f); v1 = v0;
        }
        const float4* q = reinterpret_cast<const float4*>(
            W + (size_t)le * ldw + off + k0 + lq);
        float4 w0 = q[0], w1 = q[1];

        __syncthreads();
        As[lq + 0][le] = v0.x; As[lq + 1][le] = v0.y;
        As[lq + 2][le] = v0.z; As[lq + 3][le] = v0.w;
        As[lq + 4][le] = v1.x; As[lq + 5][le] = v1.y;
        As[lq + 6][le] = v1.z; As[lq + 7][le] = v1.w;
        Bs[lq + 0][le] = w0.x; Bs[lq + 1][le] = w0.y;
        Bs[lq + 2][le] = w0.z; Bs[lq + 3][le] = w0.w;
        Bs[lq + 4][le] = w1.x; Bs[lq + 5][le] = w1.y;
        Bs[lq + 6][le] = w1.z; Bs[lq + 7][le] = w1.w;
        __syncthreads();

#pragma unroll
        for (int kk = 0; kk < 16; kk++) {
            float4 a0 = *reinterpret_cast<const float4*>(&As[kk][ty * 8]);
            float4 a1 = *reinterpret_cast<const float4*>(&As[kk][ty * 8 + 4]);
            ulonglong2 b01 = *reinterpret_cast<const ulonglong2*>(&Bs[kk][tx * 8]);
            ulonglong2 b23 = *reinterpret_cast<const ulonglong2*>(&Bs[kk][tx * 8 + 4]);
            unsigned long long av[8];
            av[0] = pack2(a0.x); av[1] = pack2(a0.y);
            av[2] = pack2(a0.z); av[3] = pack2(a0.w);
            av[4] = pack2(a1.x); av[5] = pack2(a1.y);
            av[6] = pack2(a1.z); av[7] = pack2(a1.w);
            unsigned long long bv[4] = {b01.x, b01.y, b23.x, b23.y};
#pragma unroll
            for (int i = 0; i < 8; i++)
#pragma unroll
                for (int j = 0; j < 4; j++)
                    ffma2(acc[i][j], av[i], bv[j]);
        }
    }
    __syncthreads();
}

// ---------------------------------------------------------------------------
// Node kernel: out = relu( Xc + agg @ W2[:,128:256].T )
// ---------------------------------------------------------------------------
__global__ __launch_bounds__(256) void node_kernel(
    const float* __restrict__ W2, float* __restrict__ out, int N)
{
    __shared__ __align__(16) float As[16][132];
    __shared__ __align__(16) float Bs[16][132];

    int n0 = blockIdx.x * 128;
    unsigned long long acc[8][4];
#pragma unroll
    for (int i = 0; i < 8; i++)
#pragma unroll
        for (int j = 0; j < 4; j++) acc[i][j] = 0ull;

    tile_gemm(g_agg, n0, N, W2, 384, 128, acc, As, Bs);

    int tid = threadIdx.x;
    int tx = tid & 15, ty = tid >> 4;
    int c = tx * 8;
#pragma unroll
    for (int i = 0; i < 8; i++) {
        int row = n0 + ty * 8 + i;
        if (row < N) {
            const float4* pc = reinterpret_cast<const float4*>(&g_Xc[(size_t)row * 128 + c]);
            float4 c0 = pc[0], c1 = pc[1];
            float2 p0 = unpk(acc[i][0]), p1 = unpk(acc[i][1]);
            float2 p2 = unpk(acc[i][2]), p3 = unpk(acc[i][3]);
            float4 o0, o1;
            o0.x = fmaxf(p0.x + c0.x, 0.f);
            o0.y = fmaxf(p0.y + c0.y, 0.f);
            o0.z = fmaxf(p1.x + c0.z, 0.f);
            o0.w = fmaxf(p1.y + c0.w, 0.f);
            o1.x = fmaxf(p2.x + c1.x, 0.f);
            o1.y = fmaxf(p2.y + c1.y, 0.f);
            o1.z = fmaxf(p3.x + c1.z, 0.f);
            o1.w = fmaxf(p3.y + c1.w, 0.f);
            float4* po = reinterpret_cast<float4*>(&out[(size_t)row * 128 + c]);
            po[0] = o0; po[1] = o1;
        }
    }
}

// ---------------------------------------------------------------------------
// Launch. Inputs: x, edge_index, edge_attr, u, batch, W1, b1, W2, b2.
// ---------------------------------------------------------------------------
extern "C" void kernel_launch(void* const* d_in, const int* in_sizes, int n_in,
                              void* d_out, int out_size) {
    const float* x         = (const float*)d_in[0];
    const void*  ei        = d_in[1];
    const float* edge_attr = (const float*)d_in[2];
    const float* u         = (const float*)d_in[3];
    const void*  batch     = d_in[4];
    const float* W1        = (const float*)d_in[5];
    const float* b1        = (const float*)d_in[6];
    const float* W2        = (const float*)d_in[7];
    const float* b2        = (const float*)d_in[8];
    float* out = (float*)d_out;

    int N = in_sizes[0] / FD;
    int E = in_sizes[2] / FD;
    int G = in_sizes[3] / FD;

    cudaFuncSetAttribute(edge_persist_kernel,
                         cudaFuncAttributeMaxDynamicSharedMemorySize, SM_EDGE_TOTAL);
    cudaFuncSetAttribute(precompute_mma_kernel,
                         cudaFuncAttributeMaxDynamicSharedMemorySize, SM_PRE_TOTAL);

    sniff_kernel<<<1, 1>>>((const unsigned int*)ei);

    int n4 = N * (FD / 4);
    zero_kernel<<<(n4 + 255) / 256, 256>>>(n4);

    graph_kernel<<<G, FD>>>(u, W1, b1, W2);

    dim3 pg((N + 127) / 128, 3);
    precompute_mma_kernel<<<pg, 256, SM_PRE_TOTAL>>>(x, W1, W2, b2, batch, N);

    edge_persist_kernel<<<296, 256, SM_EDGE_TOTAL>>>(edge_attr, ei, W1, E);

    node_kernel<<<(N + 127) / 128, 256>>>(W2, out, N);
}

// round 16
// speedup vs baseline: 1.0358x; 1.0238x over previous
#include <cuda_runtime.h>
#include <cuda_fp16.h>

// GraphNet NodeModel, algebraically factored:
//   Xau = x @ W1a.T + Ue[batch]   (fp16 table)
//   Xb  = x @ W1b.T               (fp16 table)
//   Xc  = x @ W2a.T + b2 + Un[batch]  (fp32)
//   edge_msg = relu( Xau[dst] + Xb[src] + edge_attr @ W1c.T )
//   agg      = segment_sum(edge_msg, dst)   (red.global.add.v4.f32)
//   out      = relu( Xc + agg @ W2b.T )
// Edge kernel: 256 edges (2 M-tiles) per block sharing ONE B stage; per-tile
// fp16 C buffer aliases that tile's dead A region. GEMMs: fp16 mma + ldmatrix.

#define FD 128
#define MAXN 50000
#define MAXG 64

__device__ __half g_Xau[MAXN * FD];  // x @ W1[:,0:128].T + Ue[batch]
__device__ __half g_Xb16[MAXN * FD]; // x @ W1[:,128:256].T
__device__ float  g_Xc[MAXN * FD];   // x @ W2[:,0:128].T + b2 + Un[batch]
__device__ float  g_agg[MAXN * FD];  // segment-summed edge messages
__device__ float  g_Ue[MAXG * FD];
__device__ float  g_Un[MAXG * FD];
__device__ int    g_is64;

// ---------------- helpers ----------------
__device__ __forceinline__ unsigned long long pack2(float x) {
    unsigned long long r;
    asm("mov.b64 %0, {%1, %1};" : "=l"(r) : "r"(__float_as_uint(x)));
    return r;
}
__device__ __forceinline__ void ffma2(unsigned long long& d,
                                      unsigned long long a,
                                      unsigned long long b) {
    asm("fma.rn.f32x2 %0, %1, %2, %0;" : "+l"(d) : "l"(a), "l"(b));
}
__device__ __forceinline__ float2 unpk(unsigned long long v) {
    float2 f;
    asm("mov.b64 {%0, %1}, %2;" : "=f"(f.x), "=f"(f.y) : "l"(v));
    return f;
}
__device__ __forceinline__ void red_add_v4(float* p, float a, float b,
                                           float c, float d) {
    unsigned long long gp = (unsigned long long)__cvta_generic_to_global(p);
    asm volatile("red.global.add.v4.f32 [%0], {%1, %2, %3, %4};"
                 :: "l"(gp), "f"(a), "f"(b), "f"(c), "f"(d) : "memory");
}
__device__ __forceinline__ long long ld_idx(const void* p, long long i, int is64) {
    if (is64) return ((const long long*)p)[i];
    return (long long)((const int*)p)[i];
}
__device__ __forceinline__ unsigned int smem_u32(const void* p) {
    unsigned int a;
    asm("{ .reg .u64 t; cvta.to.shared.u64 t, %1; cvt.u32.u64 %0, t; }"
        : "=r"(a) : "l"(p));
    return a;
}
__device__ __forceinline__ unsigned int f16pack(float2 f) {
    unsigned int h;
    asm("cvt.rn.f16x2.f32 %0, %1, %2;" : "=r"(h) : "f"(f.y), "f"(f.x));
    return h;
}
__device__ __forceinline__ void mma_f16(float& c0, float& c1, float& c2, float& c3,
                                        unsigned int a0, unsigned int a1,
                                        unsigned int a2, unsigned int a3,
                                        unsigned int b0, unsigned int b1) {
    asm volatile(
        "mma.sync.aligned.m16n8k16.row.col.f32.f16.f16.f32 "
        "{%0,%1,%2,%3}, {%4,%5,%6,%7}, {%8,%9}, {%0,%1,%2,%3};"
        : "+f"(c0), "+f"(c1), "+f"(c2), "+f"(c3)
        : "r"(a0), "r"(a1), "r"(a2), "r"(a3), "r"(b0), "r"(b1));
}
__device__ __forceinline__ void ldmatrix_x4(unsigned int& r0, unsigned int& r1,
                                            unsigned int& r2, unsigned int& r3,
                                            unsigned int addr) {
    asm volatile("ldmatrix.sync.aligned.m8n8.x4.shared.b16 {%0,%1,%2,%3}, [%4];"
                 : "=r"(r0), "=r"(r1), "=r"(r2), "=r"(r3) : "r"(addr));
}

// ---------------------------------------------------------------------------
// Index dtype sniff: int64 values < 2^31 have all-zero odd 32-bit words.
// ---------------------------------------------------------------------------
__global__ void sniff_kernel(const unsigned int* __restrict__ ei) {
    int is64 = 1;
#pragma unroll 1
    for (int k = 1; k < 129; k += 2) {
        if (ei[k] != 0u) { is64 = 0; break; }
    }
    g_is64 = is64;
}

__global__ void zero_kernel(int n4) {
    int i = blockIdx.x * blockDim.x + threadIdx.x;
    if (i < n4)
        reinterpret_cast<float4*>(g_agg)[i] = make_float4(0.f, 0.f, 0.f, 0.f);
}

// ---------------------------------------------------------------------------
// Per-graph GEMMs (tiny). Block = one graph, 128 threads, fp32.
// ---------------------------------------------------------------------------
__global__ void graph_kernel(const float* __restrict__ u,
                             const float* __restrict__ W1,
                             const float* __restrict__ b1,
                             const float* __restrict__ W2) {
    __shared__ float su[FD];
    int g = blockIdx.x;
    int o = threadIdx.x;
    su[o] = u[g * FD + o];
    __syncthreads();
    float a1 = b1[o];
    float a2 = 0.f;
    const float* w1r = W1 + o * 512 + 384;
    const float* w2r = W2 + o * 384 + 256;
#pragma unroll 8
    for (int k = 0; k < FD; k++) {
        a1 = fmaf(su[k], w1r[k], a1);
        a2 = fmaf(su[k], w2r[k], a2);
    }
    g_Ue[g * FD + o] = a1;
    g_Un[g * FD + o] = a2;
}

// ---------------------------------------------------------------------------
// fp16 warp-tile GEMM pieces (operands staged to smem, stride BSTR fp16).
// ---------------------------------------------------------------------------
#define BSTR 136
#define TILE_BYTES (128 * BSTR * 2)            // 34816
#define CSTR 132
#define SM_IDX 2048
#define SM_B   SM_IDX
#define SM_A0  (SM_B + TILE_BYTES)
#define SM_A1  (SM_A0 + TILE_BYTES)
#define SM_EDGE_TOTAL (SM_A1 + TILE_BYTES)     // 106496
#define SM_PRE_TOTAL  (2 * TILE_BYTES + 64)

__device__ __forceinline__ void stage_fp16(__half* S, const float* __restrict__ src,
                                           long long rowBase, long long M,
                                           int ldsrc, int off) {
#pragma unroll
    for (int it = 0; it < 8; it++) {
        int g = threadIdx.x + it * 256;
        int r = g >> 4;
        int c0 = (g & 15) << 3;
        uint4 out;
        long long row = rowBase + r;
        if (row < M) {
            const float4* p = reinterpret_cast<const float4*>(
                src + row * ldsrc + off + c0);
            float4 f0 = p[0], f1 = p[1];
            out = make_uint4(f16pack(make_float2(f0.x, f0.y)),
                             f16pack(make_float2(f0.z, f0.w)),
                             f16pack(make_float2(f1.x, f1.y)),
                             f16pack(make_float2(f1.z, f1.w)));
        } else {
            out = make_uint4(0u, 0u, 0u, 0u);
        }
        *reinterpret_cast<uint4*>(S + r * BSTR + c0) = out;
    }
}

__device__ __forceinline__ void mma_mainloop_sm(
    unsigned int sbA, unsigned int sbB, int wid, int lane, float (&acc)[16][4])
{
    unsigned int abase = sbA
        + (unsigned int)((wid * 16 + (lane & 15)) * (BSTR * 2))
        + (unsigned int)((lane >> 4) * 16);

    unsigned int bbase[8];
    {
        int ii = lane & 7;
        int gg = lane >> 3;
        int nthalf = gg >> 1;
        int khalf = gg & 1;
#pragma unroll
        for (int q = 0; q < 8; q++) {
            int row = (2 * q + nthalf) * 8 + ii;
            bbase[q] = sbB + (unsigned int)(row * (BSTR * 2)) + khalf * 16;
        }
    }

#pragma unroll
    for (int kc = 0; kc < 8; kc++) {
        const int koff = kc * 32;
        unsigned int a0, a1, a2, a3;
        ldmatrix_x4(a0, a1, a2, a3, abase + koff);
#pragma unroll
        for (int q = 0; q < 8; q++) {
            unsigned int b0, b1, b2, b3;
            ldmatrix_x4(b0, b1, b2, b3, bbase[q] + koff);
            mma_f16(acc[2*q][0],   acc[2*q][1],   acc[2*q][2],   acc[2*q][3],
                    a0, a1, a2, a3, b0, b1);
            mma_f16(acc[2*q+1][0], acc[2*q+1][1], acc[2*q+1][2], acc[2*q+1][3],
                    a0, a1, a2, a3, b2, b3);
        }
    }
}

// ---------------------------------------------------------------------------
// Precompute Xau / Xb16 / Xc; grid.y selects product.
// ---------------------------------------------------------------------------
__global__ __launch_bounds__(256, 2)
void precompute_mma_kernel(const float* __restrict__ x,
                           const float* __restrict__ W1,
                           const float* __restrict__ W2,
                           const float* __restrict__ b2,
                           const void* __restrict__ batch, int N)
{
    extern __shared__ __align__(16) char smem[];
    __half* Bh = (__half*)smem;
    __half* Ah = (__half*)(smem + TILE_BYTES);

    const float* W; int ldw, off;
    int which = blockIdx.y;
    if (which == 0)      { W = W1; ldw = 512; off = 0;   }
    else if (which == 1) { W = W1; ldw = 512; off = 128; }
    else                 { W = W2; ldw = 384; off = 0;   }

    const long long m0 = (long long)blockIdx.x * 128;
    stage_fp16(Bh, W, 0, 128, ldw, off);
    stage_fp16(Ah, x, m0, N, 128, 0);
    __syncthreads();

    const int tid = threadIdx.x;
    const int wid = tid >> 5;
    const int lane = tid & 31;
    const long long r0 = m0 + wid * 16 + (lane >> 2);
    const long long r1 = r0 + 8;

    float acc[16][4];
#pragma unroll
    for (int t = 0; t < 16; t++)
#pragma unroll
        for (int j = 0; j < 4; j++) acc[t][j] = 0.f;

    mma_mainloop_sm(smem_u32(Ah), smem_u32(Bh), wid, lane, acc);

    const int cb = (lane & 3) * 2;
    const int is64 = g_is64;
#pragma unroll
    for (int h = 0; h < 2; h++) {
        long long row = h ? r1 : r0;
        if (row >= N) continue;
        const float* uadd = 0;
        if (which == 0)
            uadd = g_Ue + (size_t)ld_idx(batch, row, is64) * 128;
        else if (which == 2)
            uadd = g_Un + (size_t)ld_idx(batch, row, is64) * 128;
#pragma unroll
        for (int nt = 0; nt < 16; nt++) {
            int c = nt * 8 + cb;
            float vx = acc[nt][2 * h], vy = acc[nt][2 * h + 1];
            if (uadd) { vx += uadd[c]; vy += uadd[c + 1]; }
            if (which == 2) {
                vx += b2[c]; vy += b2[c + 1];
                *reinterpret_cast<float2*>(g_Xc + row * 128 + c) = make_float2(vx, vy);
            } else {
                __half2 hv = __floats2half2_rn(vx, vy);
                __half* T = (which == 0) ? g_Xau : g_Xb16;
                *reinterpret_cast<__half2*>(T + row * 128 + c) = hv;
            }
        }
    }
}

// ---------------------------------------------------------------------------
// Edge kernel: 256 edges per block = two M=128 tiles sharing one B stage.
// Per tile: mma -> fp16 C into OWN dead A region -> sync -> epilogue -> sync.
// ---------------------------------------------------------------------------
__global__ __launch_bounds__(256, 2)
void edge_mma_kernel(const float* __restrict__ edge_attr,
                     const float* __restrict__ W1,
                     const void* __restrict__ ei, int E)
{
    extern __shared__ __align__(16) char smem[];
    int* sSrc = (int*)smem;             // [256]
    int* sDst = sSrc + 256;             // [256]
    __half* Bh = (__half*)(smem + SM_B);
    __half* Ah[2] = { (__half*)(smem + SM_A0), (__half*)(smem + SM_A1) };

    const int tid = threadIdx.x;
    const int wid = tid >> 5;
    const int lane = tid & 31;
    const long long e0 = (long long)blockIdx.x * 256;

    // indices for 256 edges
    {
        int is64 = g_is64;
        long long ge = e0 + tid;
        if (ge < E) {
            sSrc[tid] = (int)ld_idx(ei, ge, is64);
            sDst[tid] = (int)ld_idx(ei, (long long)E + ge, is64);
        } else {
            sSrc[tid] = 0; sDst[tid] = 0;
        }
    }

    stage_fp16(Bh, W1, 0, 128, 512, 256);           // W1c, once per block
    stage_fp16(Ah[0], edge_attr, e0, E, 128, 0);
    stage_fp16(Ah[1], edge_attr, e0 + 128, E, 128, 0);
    __syncthreads();

    const unsigned int sbB = smem_u32(Bh);

#pragma unroll 1
    for (int t = 0; t < 2; t++) {
        const long long eb = e0 + t * 128;
        if (eb >= E) break;
        __half* Cf = Ah[t];   // fp16 C aliases this tile's A (dead after mma)

        float acc[16][4];
#pragma unroll
        for (int q = 0; q < 16; q++)
#pragma unroll
            for (int j = 0; j < 4; j++) acc[q][j] = 0.f;

        mma_mainloop_sm(smem_u32(Ah[t]), sbB, wid, lane, acc);
        __syncthreads();   // everyone done reading A[t] before overwrite

        // write C (fp16) into A[t] region
        {
            const int rbase = wid * 16 + (lane >> 2);
            const int cb = (lane & 3) * 2;
#pragma unroll
            for (int nt = 0; nt < 16; nt++) {
                __half2 h0 = __floats2half2_rn(acc[nt][0], acc[nt][1]);
                __half2 h1 = __floats2half2_rn(acc[nt][2], acc[nt][3]);
                *reinterpret_cast<__half2*>(Cf + rbase * CSTR + nt * 8 + cb) = h0;
                *reinterpret_cast<__half2*>(Cf + (rbase + 8) * CSTR + nt * 8 + cb) = h1;
            }
        }
        __syncthreads();

        // epilogue: gathers + relu + red.v4 (2 threads per edge)
        {
            const int el = tid >> 1;
            const int cb = (tid & 1) * 64;
            const long long ge = eb + el;
            if (ge < E) {
                int li = t * 128 + el;
                int s = sSrc[li], d = sDst[li];
                const __half* xa = g_Xau + (size_t)d * 128 + cb;
                const __half* xb = g_Xb16 + (size_t)s * 128 + cb;
                const __half* cr = Cf + el * CSTR + cb;
                float* dp = g_agg + (size_t)d * 128 + cb;
#pragma unroll
                for (int j = 0; j < 8; j++) {
                    int c = j * 8;
                    uint2 mA = *reinterpret_cast<const uint2*>(cr + c);
                    uint2 mB = *reinterpret_cast<const uint2*>(cr + c + 4);
                    uint4 ua = *reinterpret_cast<const uint4*>(xa + c);
                    uint4 ub = *reinterpret_cast<const uint4*>(xb + c);
                    float2 m0 = __half22float2(*reinterpret_cast<__half2*>(&mA.x));
                    float2 m1 = __half22float2(*reinterpret_cast<__half2*>(&mA.y));
                    float2 m2 = __half22float2(*reinterpret_cast<__half2*>(&mB.x));
                    float2 m3 = __half22float2(*reinterpret_cast<__half2*>(&mB.y));
                    float2 a0 = __half22float2(*reinterpret_cast<__half2*>(&ua.x));
                    float2 a1 = __half22float2(*reinterpret_cast<__half2*>(&ua.y));
                    float2 a2 = __half22float2(*reinterpret_cast<__half2*>(&ua.z));
                    float2 a3 = __half22float2(*reinterpret_cast<__half2*>(&ua.w));
                    float2 b0 = __half22float2(*reinterpret_cast<__half2*>(&ub.x));
                    float2 b1 = __half22float2(*reinterpret_cast<__half2*>(&ub.y));
                    float2 b2 = __half22float2(*reinterpret_cast<__half2*>(&ub.z));
                    float2 b3 = __half22float2(*reinterpret_cast<__half2*>(&ub.w));
                    float w0 = fmaxf(m0.x + a0.x + b0.x, 0.f);
                    float w1 = fmaxf(m0.y + a0.y + b0.y, 0.f);
                    float w2 = fmaxf(m1.x + a1.x + b1.x, 0.f);
                    float w3 = fmaxf(m1.y + a1.y + b1.y, 0.f);
                    red_add_v4(dp + c, w0, w1, w2, w3);
                    float w4 = fmaxf(m2.x + a2.x + b2.x, 0.f);
                    float w5 = fmaxf(m2.y + a2.y + b2.y, 0.f);
                    float w6 = fmaxf(m3.x + a3.x + b3.x, 0.f);
                    float w7 = fmaxf(m3.y + a3.y + b3.y, 0.f);
                    red_add_v4(dp + c + 4, w4, w5, w6, w7);
                }
            }
        }
        __syncthreads();
    }
}

// ---------------------------------------------------------------------------
// FFMA2 tile GEMM (node kernel): 128x128xK=128, 256 threads. fp32 exact.
// ---------------------------------------------------------------------------
__device__ __forceinline__ void tile_gemm(
    const float* __restrict__ A, int rowBase, int M,
    const float* __restrict__ W, int ldw, int off,
    unsigned long long (&acc)[8][4], float (*As)[132], float (*Bs)[132])
{
    const int tid = threadIdx.x;
    const int le = tid & 127;
    const int lq = (tid >> 7) << 3;
    const int tx = tid & 15;
    const int ty = tid >> 4;

#pragma unroll 1
    for (int k0 = 0; k0 < 128; k0 += 16) {
        float4 v0, v1;
        int row = rowBase + le;
        if (row < M) {
            const float4* p = reinterpret_cast<const float4*>(
                A + (size_t)row * 128 + k0 + lq);
            v0 = p[0]; v1 = p[1];
        } else {
            v0 = make_float4(0.f, 0.f, 0.f, 0.f); v1 = v0;
        }
        const float4* q = reinterpret_cast<const float4*>(
            W + (size_t)le * ldw + off + k0 + lq);
        float4 w0 = q[0], w1 = q[1];

        __syncthreads();
        As[lq + 0][le] = v0.x; As[lq + 1][le] = v0.y;
        As[lq + 2][le] = v0.z; As[lq + 3][le] = v0.w;
        As[lq + 4][le] = v1.x; As[lq + 5][le] = v1.y;
        As[lq + 6][le] = v1.z; As[lq + 7][le] = v1.w;
        Bs[lq + 0][le] = w0.x; Bs[lq + 1][le] = w0.y;
        Bs[lq + 2][le] = w0.z; Bs[lq + 3][le] = w0.w;
        Bs[lq + 4][le] = w1.x; Bs[lq + 5][le] = w1.y;
        Bs[lq + 6][le] = w1.z; Bs[lq + 7][le] = w1.w;
        __syncthreads();

#pragma unroll
        for (int kk = 0; kk < 16; kk++) {
            float4 a0 = *reinterpret_cast<const float4*>(&As[kk][ty * 8]);
            float4 a1 = *reinterpret_cast<const float4*>(&As[kk][ty * 8 + 4]);
            ulonglong2 b01 = *reinterpret_cast<const ulonglong2*>(&Bs[kk][tx * 8]);
            ulonglong2 b23 = *reinterpret_cast<const ulonglong2*>(&Bs[kk][tx * 8 + 4]);
            unsigned long long av[8];
            av[0] = pack2(a0.x); av[1] = pack2(a0.y);
            av[2] = pack2(a0.z); av[3] = pack2(a0.w);
            av[4] = pack2(a1.x); av[5] = pack2(a1.y);
            av[6] = pack2(a1.z); av[7] = pack2(a1.w);
            unsigned long long bv[4] = {b01.x, b01.y, b23.x, b23.y};
#pragma unroll
            for (int i = 0; i < 8; i++)
#pragma unroll
                for (int j = 0; j < 4; j++)
                    ffma2(acc[i][j], av[i], bv[j]);
        }
    }
    __syncthreads();
}

// ---------------------------------------------------------------------------
// Node kernel: out = relu( Xc + agg @ W2[:,128:256].T )
// ---------------------------------------------------------------------------
__global__ __launch_bounds__(256) void node_kernel(
    const float* __restrict__ W2, float* __restrict__ out, int N)
{
    __shared__ __align__(16) float As[16][132];
    __shared__ __align__(16) float Bs[16][132];

    int n0 = blockIdx.x * 128;
    unsigned long long acc[8][4];
#pragma unroll
    for (int i = 0; i < 8; i++)
#pragma unroll
        for (int j = 0; j < 4; j++) acc[i][j] = 0ull;

    tile_gemm(g_agg, n0, N, W2, 384, 128, acc, As, Bs);

    int tid = threadIdx.x;
    int tx = tid & 15, ty = tid >> 4;
    int c = tx * 8;
#pragma unroll
    for (int i = 0; i < 8; i++) {
        int row = n0 + ty * 8 + i;
        if (row < N) {
            const float4* pc = reinterpret_cast<const float4*>(&g_Xc[(size_t)row * 128 + c]);
            float4 c0 = pc[0], c1 = pc[1];
            float2 p0 = unpk(acc[i][0]), p1 = unpk(acc[i][1]);
            float2 p2 = unpk(acc[i][2]), p3 = unpk(acc[i][3]);
            float4 o0, o1;
            o0.x = fmaxf(p0.x + c0.x, 0.f);
            o0.y = fmaxf(p0.y + c0.y, 0.f);
            o0.z = fmaxf(p1.x + c0.z, 0.f);
            o0.w = fmaxf(p1.y + c0.w, 0.f);
            o1.x = fmaxf(p2.x + c1.x, 0.f);
            o1.y = fmaxf(p2.y + c1.y, 0.f);
            o1.z = fmaxf(p3.x + c1.z, 0.f);
            o1.w = fmaxf(p3.y + c1.w, 0.f);
            float4* po = reinterpret_cast<float4*>(&out[(size_t)row * 128 + c]);
            po[0] = o0; po[1] = o1;
        }
    }
}

// ---------------------------------------------------------------------------
// Launch. Inputs: x, edge_index, edge_attr, u, batch, W1, b1, W2, b2.
// ---------------------------------------------------------------------------
extern "C" void kernel_launch(void* const* d_in, const int* in_sizes, int n_in,
                              void* d_out, int out_size) {
    const float* x         = (const float*)d_in[0];
    const void*  ei        = d_in[1];
    const float* edge_attr = (const float*)d_in[2];
    const float* u         = (const float*)d_in[3];
    const void*  batch     = d_in[4];
    const float* W1        = (const float*)d_in[5];
    const float* b1        = (const float*)d_in[6];
    const float* W2        = (const float*)d_in[7];
    const float* b2        = (const float*)d_in[8];
    float* out = (float*)d_out;

    int N = in_sizes[0] / FD;
    int E = in_sizes[2] / FD;
    int G = in_sizes[3] / FD;

    cudaFuncSetAttribute(edge_mma_kernel,
                         cudaFuncAttributeMaxDynamicSharedMemorySize, SM_EDGE_TOTAL);
    cudaFuncSetAttribute(precompute_mma_kernel,
                         cudaFuncAttributeMaxDynamicSharedMemorySize, SM_PRE_TOTAL);

    sniff_kernel<<<1, 1>>>((const unsigned int*)ei);

    int n4 = N * (FD / 4);
    zero_kernel<<<(n4 + 255) / 256, 256>>>(n4);

    graph_kernel<<<G, FD>>>(u, W1, b1, W2);

    dim3 pg((N + 127) / 128, 3);
    precompute_mma_kernel<<<pg, 256, SM_PRE_TOTAL>>>(x, W1, W2, b2, batch, N);

    edge_mma_kernel<<<(E + 255) / 256, 256, SM_EDGE_TOTAL>>>(edge_attr, W1, ei, E);

    node_kernel<<<(N + 127) / 128, 256>>>(W2, out, N);
}

// round 17
// speedup vs baseline: 1.1557x; 1.1158x over previous
#include <cuda_runtime.h>
#include <cuda_fp16.h>

// GraphNet NodeModel, algebraically factored:
//   Xau = x @ W1a.T + Ue[batch]   (fp16 table)
//   Xb  = x @ W1b.T               (fp16 table)
//   Xc  = x @ W2a.T + b2 + Un[batch]  (fp32)
//   edge_msg = relu( Xau[dst] + Xb[src] + edge_attr @ W1c.T )
//   agg      = segment_sum(edge_msg, dst)   (red.global.add.v4.f32)
//   out      = relu( Xc + agg @ W2b.T )
// Round-12 champion shape; weight blocks pre-converted to fp16 ONCE so the
// per-block B stage is a pure smem copy (no cvt, half the load bytes).

#define FD 128
#define MAXN 50000
#define MAXG 64

__device__ __half g_Xau[MAXN * FD];  // x @ W1[:,0:128].T + Ue[batch]
__device__ __half g_Xb16[MAXN * FD]; // x @ W1[:,128:256].T
__device__ float  g_Xc[MAXN * FD];   // x @ W2[:,0:128].T + b2 + Un[batch]
__device__ float  g_agg[MAXN * FD];  // segment-summed edge messages
__device__ float  g_Ue[MAXG * FD];
__device__ float  g_Un[MAXG * FD];
__device__ __half g_W16[4 * 16384];  // fp16 weights: 0=W1a 1=W1b 2=W2a 3=W1c
__device__ int    g_is64;

// ---------------- helpers ----------------
__device__ __forceinline__ unsigned long long pack2(float x) {
    unsigned long long r;
    asm("mov.b64 %0, {%1, %1};" : "=l"(r) : "r"(__float_as_uint(x)));
    return r;
}
__device__ __forceinline__ void ffma2(unsigned long long& d,
                                      unsigned long long a,
                                      unsigned long long b) {
    asm("fma.rn.f32x2 %0, %1, %2, %0;" : "+l"(d) : "l"(a), "l"(b));
}
__device__ __forceinline__ float2 unpk(unsigned long long v) {
    float2 f;
    asm("mov.b64 {%0, %1}, %2;" : "=f"(f.x), "=f"(f.y) : "l"(v));
    return f;
}
__device__ __forceinline__ void red_add_v4(float* p, float a, float b,
                                           float c, float d) {
    unsigned long long gp = (unsigned long long)__cvta_generic_to_global(p);
    asm volatile("red.global.add.v4.f32 [%0], {%1, %2, %3, %4};"
                 :: "l"(gp), "f"(a), "f"(b), "f"(c), "f"(d) : "memory");
}
__device__ __forceinline__ long long ld_idx(const void* p, long long i, int is64) {
    if (is64) return ((const long long*)p)[i];
    return (long long)((const int*)p)[i];
}
__device__ __forceinline__ unsigned int smem_u32(const void* p) {
    unsigned int a;
    asm("{ .reg .u64 t; cvta.to.shared.u64 t, %1; cvt.u32.u64 %0, t; }"
        : "=r"(a) : "l"(p));
    return a;
}
__device__ __forceinline__ unsigned int f16pack(float2 f) {
    unsigned int h;
    asm("cvt.rn.f16x2.f32 %0, %1, %2;" : "=r"(h) : "f"(f.y), "f"(f.x));
    return h;
}
__device__ __forceinline__ void mma_f16(float& c0, float& c1, float& c2, float& c3,
                                        unsigned int a0, unsigned int a1,
                                        unsigned int a2, unsigned int a3,
                                        unsigned int b0, unsigned int b1) {
    asm volatile(
        "mma.sync.aligned.m16n8k16.row.col.f32.f16.f16.f32 "
        "{%0,%1,%2,%3}, {%4,%5,%6,%7}, {%8,%9}, {%0,%1,%2,%3};"
        : "+f"(c0), "+f"(c1), "+f"(c2), "+f"(c3)
        : "r"(a0), "r"(a1), "r"(a2), "r"(a3), "r"(b0), "r"(b1));
}
__device__ __forceinline__ void ldmatrix_x4(unsigned int& r0, unsigned int& r1,
                                            unsigned int& r2, unsigned int& r3,
                                            unsigned int addr) {
    asm volatile("ldmatrix.sync.aligned.m8n8.x4.shared.b16 {%0,%1,%2,%3}, [%4];"
                 : "=r"(r0), "=r"(r1), "=r"(r2), "=r"(r3) : "r"(addr));
}

// ---------------------------------------------------------------------------
// Index dtype sniff: int64 values < 2^31 have all-zero odd 32-bit words.
// ---------------------------------------------------------------------------
__global__ void sniff_kernel(const unsigned int* __restrict__ ei) {
    int is64 = 1;
#pragma unroll 1
    for (int k = 1; k < 129; k += 2) {
        if (ei[k] != 0u) { is64 = 0; break; }
    }
    g_is64 = is64;
}

__global__ void zero_kernel(int n4) {
    int i = blockIdx.x * blockDim.x + threadIdx.x;
    if (i < n4)
        reinterpret_cast<float4*>(g_agg)[i] = make_float4(0.f, 0.f, 0.f, 0.f);
}

// One-shot fp16 conversion of the four 128x128 weight blocks.
// grid (64, 4), block 256. Rounding identical to the old per-block cvt.rn.
__global__ void convert_w_kernel(const float* __restrict__ W1,
                                 const float* __restrict__ W2) {
    int idx = blockIdx.x * 256 + threadIdx.x;   // 0..16383
    int r = idx >> 7;
    int c = idx & 127;
    int wb = blockIdx.y;
    float v;
    if (wb == 0)      v = W1[r * 512 + c];
    else if (wb == 1) v = W1[r * 512 + 128 + c];
    else if (wb == 2) v = W2[r * 384 + c];
    else              v = W1[r * 512 + 256 + c];
    g_W16[wb * 16384 + idx] = __float2half_rn(v);
}

// ---------------------------------------------------------------------------
// Per-graph GEMMs (tiny). Block = one graph, 128 threads, fp32.
// ---------------------------------------------------------------------------
__global__ void graph_kernel(const float* __restrict__ u,
                             const float* __restrict__ W1,
                             const float* __restrict__ b1,
                             const float* __restrict__ W2) {
    __shared__ float su[FD];
    int g = blockIdx.x;
    int o = threadIdx.x;
    su[o] = u[g * FD + o];
    __syncthreads();
    float a1 = b1[o];
    float a2 = 0.f;
    const float* w1r = W1 + o * 512 + 384;
    const float* w2r = W2 + o * 384 + 256;
#pragma unroll 8
    for (int k = 0; k < FD; k++) {
        a1 = fmaf(su[k], w1r[k], a1);
        a2 = fmaf(su[k], w2r[k], a2);
    }
    g_Ue[g * FD + o] = a1;
    g_Un[g * FD + o] = a2;
}

// ---------------------------------------------------------------------------
// fp16 warp-tile GEMM pieces. Operands staged to smem (stride BSTR fp16).
// ---------------------------------------------------------------------------
#define BSTR 136
#define TILE_BYTES (128 * BSTR * 2)
#define SM_B   2048
#define SM_A   (SM_B + TILE_BYTES)
#define SM_EDGE_TOTAL (SM_A + TILE_BYTES)      // 71680
#define SM_PRE_TOTAL  (2 * TILE_BYTES + 64)

// Stage a 128x128 fp32 block into fp16 smem (MLP 16 per thread).
__device__ __forceinline__ void stage_fp16(__half* S, const float* __restrict__ src,
                                           long long rowBase, long long M,
                                           int ldsrc, int off) {
#pragma unroll
    for (int it = 0; it < 8; it++) {
        int g = threadIdx.x + it * 256;
        int r = g >> 4;
        int c0 = (g & 15) << 3;
        uint4 out;
        long long row = rowBase + r;
        if (row < M) {
            const float4* p = reinterpret_cast<const float4*>(
                src + row * ldsrc + off + c0);
            float4 f0 = p[0], f1 = p[1];
            out = make_uint4(f16pack(make_float2(f0.x, f0.y)),
                             f16pack(make_float2(f0.z, f0.w)),
                             f16pack(make_float2(f1.x, f1.y)),
                             f16pack(make_float2(f1.z, f1.w)));
        } else {
            out = make_uint4(0u, 0u, 0u, 0u);
        }
        *reinterpret_cast<uint4*>(S + r * BSTR + c0) = out;
    }
}

// Stage a pre-converted fp16 128x128 block: pure 16-byte copies.
__device__ __forceinline__ void stage_copy16(__half* S, const __half* __restrict__ src) {
#pragma unroll
    for (int it = 0; it < 8; it++) {
        int g = threadIdx.x + it * 256;
        int r = g >> 4;
        int c0 = (g & 15) << 3;
        *reinterpret_cast<uint4*>(S + r * BSTR + c0) =
            *reinterpret_cast<const uint4*>(src + r * 128 + c0);
    }
}

__device__ __forceinline__ void mma_mainloop_sm(
    unsigned int sbA, unsigned int sbB, int wid, int lane, float (&acc)[16][4])
{
    unsigned int abase = sbA
        + (unsigned int)((wid * 16 + (lane & 15)) * (BSTR * 2))
        + (unsigned int)((lane >> 4) * 16);

    unsigned int bbase[8];
    {
        int ii = lane & 7;
        int gg = lane >> 3;
        int nthalf = gg >> 1;
        int khalf = gg & 1;
#pragma unroll
        for (int q = 0; q < 8; q++) {
            int row = (2 * q + nthalf) * 8 + ii;
            bbase[q] = sbB + (unsigned int)(row * (BSTR * 2)) + khalf * 16;
        }
    }

#pragma unroll
    for (int kc = 0; kc < 8; kc++) {
        const int koff = kc * 32;
        unsigned int a0, a1, a2, a3;
        ldmatrix_x4(a0, a1, a2, a3, abase + koff);
#pragma unroll
        for (int q = 0; q < 8; q++) {
            unsigned int b0, b1, b2, b3;
            ldmatrix_x4(b0, b1, b2, b3, bbase[q] + koff);
            mma_f16(acc[2*q][0],   acc[2*q][1],   acc[2*q][2],   acc[2*q][3],
                    a0, a1, a2, a3, b0, b1);
            mma_f16(acc[2*q+1][0], acc[2*q+1][1], acc[2*q+1][2], acc[2*q+1][3],
                    a0, a1, a2, a3, b2, b3);
        }
    }
}

// ---------------------------------------------------------------------------
// Precompute Xau / Xb16 / Xc; grid.y selects product. B from g_W16 (copy).
// ---------------------------------------------------------------------------
__global__ __launch_bounds__(256, 2)
void precompute_mma_kernel(const float* __restrict__ x,
                           const float* __restrict__ b2,
                           const void* __restrict__ batch, int N)
{
    extern __shared__ __align__(16) char smem[];
    __half* Bh = (__half*)smem;
    __half* Ah = (__half*)(smem + TILE_BYTES);

    int which = blockIdx.y;   // 0=W1a, 1=W1b, 2=W2a

    const long long m0 = (long long)blockIdx.x * 128;
    stage_copy16(Bh, g_W16 + which * 16384);
    stage_fp16(Ah, x, m0, N, 128, 0);
    __syncthreads();

    const int tid = threadIdx.x;
    const int wid = tid >> 5;
    const int lane = tid & 31;
    const long long r0 = m0 + wid * 16 + (lane >> 2);
    const long long r1 = r0 + 8;

    float acc[16][4];
#pragma unroll
    for (int t = 0; t < 16; t++)
#pragma unroll
        for (int j = 0; j < 4; j++) acc[t][j] = 0.f;

    mma_mainloop_sm(smem_u32(Ah), smem_u32(Bh), wid, lane, acc);

    const int cb = (lane & 3) * 2;
    const int is64 = g_is64;
#pragma unroll
    for (int h = 0; h < 2; h++) {
        long long row = h ? r1 : r0;
        if (row >= N) continue;
        const float* uadd = 0;
        if (which == 0)
            uadd = g_Ue + (size_t)ld_idx(batch, row, is64) * 128;
        else if (which == 2)
            uadd = g_Un + (size_t)ld_idx(batch, row, is64) * 128;
#pragma unroll
        for (int nt = 0; nt < 16; nt++) {
            int c = nt * 8 + cb;
            float vx = acc[nt][2 * h], vy = acc[nt][2 * h + 1];
            if (uadd) { vx += uadd[c]; vy += uadd[c + 1]; }
            if (which == 2) {
                vx += b2[c]; vy += b2[c + 1];
                *reinterpret_cast<float2*>(g_Xc + row * 128 + c) = make_float2(vx, vy);
            } else {
                __half2 hv = __floats2half2_rn(vx, vy);
                __half* T = (which == 0) ? g_Xau : g_Xb16;
                *reinterpret_cast<__half2*>(T + row * 128 + c) = hv;
            }
        }
    }
}

// ---------------------------------------------------------------------------
// Edge kernel (round-12 shape): 128 edges/block; Ea via fp16 mma; C staged
// through smem (fp32, aliases A+B); epilogue gathers fp16 Xau[dst]+Xb[src],
// relu, red.global.add.v4. B copied from pre-converted g_W16[3].
// ---------------------------------------------------------------------------
__global__ __launch_bounds__(256, 2)
void edge_mma_kernel(const float* __restrict__ edge_attr,
                     const void* __restrict__ ei, int E)
{
    extern __shared__ __align__(16) char smem[];
    int* sDst = (int*)smem;
    int* sSrc = sDst + 128;
    __half* Bh = (__half*)(smem + SM_B);
    __half* Ah = (__half*)(smem + SM_A);
    float* Cbuf = (float*)(smem + SM_B);          // [128][132], aliases A+B

    const int tid = threadIdx.x;
    const int wid = tid >> 5;
    const int lane = tid & 31;
    const long long e0 = (long long)blockIdx.x * 128;

    // indices
    if (tid < 128) {
        int is64 = g_is64;
        long long ge = e0 + tid;
        if (ge < E) {
            sSrc[tid] = (int)ld_idx(ei, ge, is64);
            sDst[tid] = (int)ld_idx(ei, (long long)E + ge, is64);
        } else {
            sSrc[tid] = 0; sDst[tid] = 0;
        }
    }

    stage_copy16(Bh, g_W16 + 3 * 16384);      // W1c, pre-converted
    stage_fp16(Ah, edge_attr, e0, E, 128, 0);
    __syncthreads();

    float acc[16][4];
#pragma unroll
    for (int t = 0; t < 16; t++)
#pragma unroll
        for (int j = 0; j < 4; j++) acc[t][j] = 0.f;

    mma_mainloop_sm(smem_u32(Ah), smem_u32(Bh), wid, lane, acc);

    // ---- stage C to smem (A/B no longer needed) ----
    __syncthreads();
    {
        const int rbase = wid * 16 + (lane >> 2);
        const int cb = (lane & 3) * 2;
#pragma unroll
        for (int nt = 0; nt < 16; nt++) {
            float* p0 = Cbuf + rbase * 132 + nt * 8 + cb;
            *reinterpret_cast<float2*>(p0)           = make_float2(acc[nt][0], acc[nt][1]);
            *reinterpret_cast<float2*>(p0 + 8 * 132) = make_float2(acc[nt][2], acc[nt][3]);
        }
    }
    __syncthreads();

    // ---- epilogue: fp16 uint4 gathers + relu + red.v4 (2 threads/edge) ----
    {
        const int el = tid >> 1;
        const int cb = (tid & 1) * 64;
        if (e0 + el < E) {
            int d = sDst[el], s = sSrc[el];
            const __half* xa = g_Xau + (size_t)d * 128 + cb;
            const __half* xb = g_Xb16 + (size_t)s * 128 + cb;
            float* dp = g_agg + (size_t)d * 128 + cb;
            const float* cr = Cbuf + el * 132 + cb;
#pragma unroll
            for (int j = 0; j < 8; j++) {
                int c = j * 8;
                float4 m0 = *reinterpret_cast<const float4*>(cr + c);
                float4 m1 = *reinterpret_cast<const float4*>(cr + c + 4);
                uint4 ua = *reinterpret_cast<const uint4*>(xa + c);
                uint4 ub = *reinterpret_cast<const uint4*>(xb + c);
                float2 a0 = __half22float2(*reinterpret_cast<__half2*>(&ua.x));
                float2 a1 = __half22float2(*reinterpret_cast<__half2*>(&ua.y));
                float2 a2 = __half22float2(*reinterpret_cast<__half2*>(&ua.z));
                float2 a3 = __half22float2(*reinterpret_cast<__half2*>(&ua.w));
                float2 b0 = __half22float2(*reinterpret_cast<__half2*>(&ub.x));
                float2 b1 = __half22float2(*reinterpret_cast<__half2*>(&ub.y));
                float2 b2 = __half22float2(*reinterpret_cast<__half2*>(&ub.z));
                float2 b3 = __half22float2(*reinterpret_cast<__half2*>(&ub.w));
                float w0 = fmaxf(m0.x + a0.x + b0.x, 0.f);
                float w1 = fmaxf(m0.y + a0.y + b0.y, 0.f);
                float w2 = fmaxf(m0.z + a1.x + b1.x, 0.f);
                float w3 = fmaxf(m0.w + a1.y + b1.y, 0.f);
                red_add_v4(dp + c, w0, w1, w2, w3);
                float w4 = fmaxf(m1.x + a2.x + b2.x, 0.f);
                float w5 = fmaxf(m1.y + a2.y + b2.y, 0.f);
                float w6 = fmaxf(m1.z + a3.x + b3.x, 0.f);
                float w7 = fmaxf(m1.w + a3.y + b3.y, 0.f);
                red_add_v4(dp + c + 4, w4, w5, w6, w7);
            }
        }
    }
}

// ---------------------------------------------------------------------------
// FFMA2 tile GEMM (node kernel): 128x128xK=128, 256 threads. fp32 exact.
// ---------------------------------------------------------------------------
__device__ __forceinline__ void tile_gemm(
    const float* __restrict__ A, int rowBase, int M,
    const float* __restrict__ W, int ldw, int off,
    unsigned long long (&acc)[8][4], float (*As)[132], float (*Bs)[132])
{
    const int tid = threadIdx.x;
    const int le = tid & 127;
    const int lq = (tid >> 7) << 3;
    const int tx = tid & 15;
    const int ty = tid >> 4;

#pragma unroll 1
    for (int k0 = 0; k0 < 128; k0 += 16) {
        float4 v0, v1;
        int row = rowBase + le;
        if (row < M) {
            const float4* p = reinterpret_cast<const float4*>(
                A + (size_t)row * 128 + k0 + lq);
            v0 = p[0]; v1 = p[1];
        } else {
            v0 = make_float4(0.f, 0.f, 0.f, 0.f); v1 = v0;
        }
        const float4* q = reinterpret_cast<const float4*>(
            W + (size_t)le * ldw + off + k0 + lq);
        float4 w0 = q[0], w1 = q[1];

        __syncthreads();
        As[lq + 0][le] = v0.x; As[lq + 1][le] = v0.y;
        As[lq + 2][le] = v0.z; As[lq + 3][le] = v0.w;
        As[lq + 4][le] = v1.x; As[lq + 5][le] = v1.y;
        As[lq + 6][le] = v1.z; As[lq + 7][le] = v1.w;
        Bs[lq + 0][le] = w0.x; Bs[lq + 1][le] = w0.y;
        Bs[lq + 2][le] = w0.z; Bs[lq + 3][le] = w0.w;
        Bs[lq + 4][le] = w1.x; Bs[lq + 5][le] = w1.y;
        Bs[lq + 6][le] = w1.z; Bs[lq + 7][le] = w1.w;
        __syncthreads();

#pragma unroll
        for (int kk = 0; kk < 16; kk++) {
            float4 a0 = *reinterpret_cast<const float4*>(&As[kk][ty * 8]);
            float4 a1 = *reinterpret_cast<const float4*>(&As[kk][ty * 8 + 4]);
            ulonglong2 b01 = *reinterpret_cast<const ulonglong2*>(&Bs[kk][tx * 8]);
            ulonglong2 b23 = *reinterpret_cast<const ulonglong2*>(&Bs[kk][tx * 8 + 4]);
            unsigned long long av[8];
            av[0] = pack2(a0.x); av[1] = pack2(a0.y);
            av[2] = pack2(a0.z); av[3] = pack2(a0.w);
            av[4] = pack2(a1.x); av[5] = pack2(a1.y);
            av[6] = pack2(a1.z); av[7] = pack2(a1.w);
            unsigned long long bv[4] = {b01.x, b01.y, b23.x, b23.y};
#pragma unroll
            for (int i = 0; i < 8; i++)
#pragma unroll
                for (int j = 0; j < 4; j++)
                    ffma2(acc[i][j], av[i], bv[j]);
        }
    }
    __syncthreads();
}

// ---------------------------------------------------------------------------
// Node kernel: out = relu( Xc + agg @ W2[:,128:256].T )
// ---------------------------------------------------------------------------
__global__ __launch_bounds__(256) void node_kernel(
    const float* __restrict__ W2, float* __restrict__ out, int N)
{
    __shared__ __align__(16) float As[16][132];
    __shared__ __align__(16) float Bs[16][132];

    int n0 = blockIdx.x * 128;
    unsigned long long acc[8][4];
#pragma unroll
    for (int i = 0; i < 8; i++)
#pragma unroll
        for (int j = 0; j < 4; j++) acc[i][j] = 0ull;

    tile_gemm(g_agg, n0, N, W2, 384, 128, acc, As, Bs);

    int tid = threadIdx.x;
    int tx = tid & 15, ty = tid >> 4;
    int c = tx * 8;
#pragma unroll
    for (int i = 0; i < 8; i++) {
        int row = n0 + ty * 8 + i;
        if (row < N) {
            const float4* pc = reinterpret_cast<const float4*>(&g_Xc[(size_t)row * 128 + c]);
            float4 c0 = pc[0], c1 = pc[1];
            float2 p0 = unpk(acc[i][0]), p1 = unpk(acc[i][1]);
            float2 p2 = unpk(acc[i][2]), p3 = unpk(acc[i][3]);
            float4 o0, o1;
            o0.x = fmaxf(p0.x + c0.x, 0.f);
            o0.y = fmaxf(p0.y + c0.y, 0.f);
            o0.z = fmaxf(p1.x + c0.z, 0.f);
            o0.w = fmaxf(p1.y + c0.w, 0.f);
            o1.x = fmaxf(p2.x + c1.x, 0.f);
            o1.y = fmaxf(p2.y + c1.y, 0.f);
            o1.z = fmaxf(p3.x + c1.z, 0.f);
            o1.w = fmaxf(p3.y + c1.w, 0.f);
            float4* po = reinterpret_cast<float4*>(&out[(size_t)row * 128 + c]);
            po[0] = o0; po[1] = o1;
        }
    }
}

// ---------------------------------------------------------------------------
// Launch. Inputs: x, edge_index, edge_attr, u, batch, W1, b1, W2, b2.
// ---------------------------------------------------------------------------
extern "C" void kernel_launch(void* const* d_in, const int* in_sizes, int n_in,
                              void* d_out, int out_size) {
    const float* x         = (const float*)d_in[0];
    const void*  ei        = d_in[1];
    const float* edge_attr = (const float*)d_in[2];
    const float* u         = (const float*)d_in[3];
    const void*  batch     = d_in[4];
    const float* W1        = (const float*)d_in[5];
    const float* b1        = (const float*)d_in[6];
    const float* W2        = (const float*)d_in[7];
    const float* b2        = (const float*)d_in[8];
    float* out = (float*)d_out;

    int N = in_sizes[0] / FD;
    int E = in_sizes[2] / FD;
    int G = in_sizes[3] / FD;

    cudaFuncSetAttribute(edge_mma_kernel,
                         cudaFuncAttributeMaxDynamicSharedMemorySize, SM_EDGE_TOTAL);
    cudaFuncSetAttribute(precompute_mma_kernel,
                         cudaFuncAttributeMaxDynamicSharedMemorySize, SM_PRE_TOTAL);

    sniff_kernel<<<1, 1>>>((const unsigned int*)ei);

    int n4 = N * (FD / 4);
    zero_kernel<<<(n4 + 255) / 256, 256>>>(n4);

    dim3 cw(64, 4);
    convert_w_kernel<<<cw, 256>>>(W1, W2);

    graph_kernel<<<G, FD>>>(u, W1, b1, W2);

    dim3 pg((N + 127) / 128, 3);
    precompute_mma_kernel<<<pg, 256, SM_PRE_TOTAL>>>(x, b2, batch, N);

    edge_mma_kernel<<<(E + 127) / 128, 256, SM_EDGE_TOTAL>>>(edge_attr, ei, E);

    node_kernel<<<(N + 127) / 128, 256>>>(W2, out, N);
}